// round 9
// baseline (speedup 1.0000x reference)
#include <cuda_runtime.h>
#include <math_constants.h>
#include <cstdint>

#define BB 64
#define DD 256
#define OO 1024
#define KK 1024

#define OT  64               // o-tile per CTA
#define KT  128              // k-tile per outer iteration
#define NKT (KK / KT)        // 8
#define DC  32               // d per staged B chunk
#define NDC (DD / DC)        // 8
#define NG  (NKT * NDC)      // 64 pipeline iterations
#define NT  256              // 8 warps: 2 (o) x 4 (k)

#define SA 260               // A row stride (floats): [o][d], pad -> conflict-free
#define SB 136               // B row stride (floats): [d][k], pad -> conflict-free

// smem layout (floats)
#define AHI   0                        // [64][260]
#define ALO   (AHI + OT * SA)          // 16640
#define BBUF  (ALO + OT * SA)          // 33280: [2 buf][2 hl][32][136]
#define BUFSZ (2 * DC * SB)            // 8704 floats per buffer (hi+lo)
#define REDV  (BBUF + 2 * BUFSZ)       // 50688: [4][64] float
#define REDK  (REDV + 256)
#define KSO   (REDK + 256)
#define SM_FLOATS (KSO + 64)           // 51264
#define SM_BYTES  (SM_FLOATS * 4)      // 205056 (< 227 KB)

// Prep scratch: ||e||^2 and pre-split emb (hi/lo), 2 MB total -> L2 resident.
__device__ float g_e2[KK];
__device__ float g_ehi[DD * KK];
__device__ float g_elo[DD * KK];

// m16n8k8 tf32 MMA (sm_80+ encoding -> compiles on plain sm_100).
#define MMA(c, a, b)                                                          \
    asm volatile(                                                             \
        "mma.sync.aligned.m16n8k8.row.col.f32.tf32.tf32.f32 "                 \
        "{%0,%1,%2,%3}, {%4,%5,%6,%7}, {%8,%9}, {%0,%1,%2,%3};"               \
        : "+f"((c)[0]), "+f"((c)[1]), "+f"((c)[2]), "+f"((c)[3])              \
        : "r"((a)[0]), "r"((a)[1]), "r"((a)[2]), "r"((a)[3]),                 \
          "r"((b)[0]), "r"((b)[1]))

#define CP16(s, g) \
    asm volatile("cp.async.cg.shared.global [%0], [%1], 16;" :: "r"(s), "l"(g))
#define CP_COMMIT() asm volatile("cp.async.commit_group;" ::: "memory")
#define CP_WAIT1()  asm volatile("cp.async.wait_group 1;" ::: "memory")
#define CP_WAIT0()  asm volatile("cp.async.wait_group 0;" ::: "memory")

__device__ __forceinline__ uint32_t smem_u32(const void* p) {
    uint32_t a;
    asm("{ .reg .u64 t; cvta.to.shared.u64 t, %1; cvt.u32.u64 %0, t; }" : "=r"(a) : "l"(p));
    return a;
}

__device__ __forceinline__ void tf32_split(float v, float& hi, float& lo) {
    uint32_t h;
    asm("cvt.rna.tf32.f32 %0, %1;" : "=r"(h) : "f"(v));
    hi = __uint_as_float(h);
    float r = v - hi;
    uint32_t l;
    asm("cvt.rna.tf32.f32 %0, %1;" : "=r"(l) : "f"(r));
    lo = __uint_as_float(l);
}

// ---------------------------------------------------------------------------
__global__ void e2_kernel(const float* __restrict__ emb) {
    int k = blockIdx.x * blockDim.x + threadIdx.x;
    float s = 0.f;
#pragma unroll 8
    for (int d = 0; d < DD; ++d) {
        float v = emb[d * KK + k];
        s = fmaf(v, v, s);
    }
    g_e2[k] = s;
}

// Pre-split emb into tf32 hi/lo (done once; kills 1024x redundant cvt work).
__global__ void split_emb_kernel(const float* __restrict__ emb) {
    int i = blockIdx.x * blockDim.x + threadIdx.x;   // over DD*KK/4 float4
    float4 v = reinterpret_cast<const float4*>(emb)[i];
    float h0, l0, h1, l1, h2, l2, h3, l3;
    tf32_split(v.x, h0, l0); tf32_split(v.y, h1, l1);
    tf32_split(v.z, h2, l2); tf32_split(v.w, h3, l3);
    reinterpret_cast<float4*>(g_ehi)[i] = make_float4(h0, h1, h2, h3);
    reinterpret_cast<float4*>(g_elo)[i] = make_float4(l0, l1, l2, l3);
}

// ---------------------------------------------------------------------------
// Fused 3xTF32 mma.sync GEMM + running argmin + gather.
// CTA: one b x 64 o. Full A (x) split resides in smem; B (emb) streamed via
// double-buffered cp.async from the pre-split global copies.
// ---------------------------------------------------------------------------
extern __shared__ float sm[];

__global__ __launch_bounds__(NT, 1)
void vq_tc(const float* __restrict__ x, const float* __restrict__ emb,
           float* __restrict__ quant, float* __restrict__ argout) {
    const int tid  = threadIdx.x;
    const int lane = tid & 31;
    const int wid  = tid >> 5;
    const int wo   = wid & 1;       // o half
    const int wk   = wid >> 1;      // k quarter
    const int b    = blockIdx.y;
    const int o0   = blockIdx.x * OT;
    const int l4   = lane & 3;
    const int lr   = lane >> 2;

    const uint32_t sb = smem_u32(sm);

    // ---- stage full A (64 o x 256 d), split to tf32 hi/lo, layout [o][SA]
    {
        const float4* x4 = reinterpret_cast<const float4*>(x + (size_t)b * DD * OO);
#pragma unroll
        for (int it = 0; it < 16; ++it) {
            int idx = tid + it * NT;               // 4096 float4: 256d x 16(o/4)
            int d = idx >> 4, o4 = idx & 15;
            float4 v = x4[(size_t)d * (OO / 4) + (o0 >> 2) + o4];
            float h, l;
            const float vv[4] = {v.x, v.y, v.z, v.w};
#pragma unroll
            for (int i = 0; i < 4; ++i) {
                tf32_split(vv[i], h, l);
                sm[AHI + (o4 * 4 + i) * SA + d] = h;
                sm[ALO + (o4 * 4 + i) * SA + d] = l;
            }
        }
    }

    // ---- B stage issuer: iteration g = kt*NDC + dc, buffer g&1
    auto issue_B = [&](int g) {
        const int ktn = g >> 3, dcn = g & 7, buf = g & 1;
#pragma unroll
        for (int it = 0; it < 8; ++it) {
            int c = tid + it * NT;                 // 2048 16B-chunks
            int hl  = c >> 10;
            int rem = c & 1023;
            int d   = rem >> 5;
            int kc  = rem & 31;                    // 16B chunk within 128-k row
            const float* gsrc = (hl ? g_elo : g_ehi)
                + (size_t)(dcn * DC + d) * KK + ktn * KT + kc * 4;
            uint32_t sdst = sb + (BBUF + buf * BUFSZ + hl * (DC * SB)
                                  + d * SB + kc * 4) * 4;
            CP16(sdst, gsrc);
        }
    };

    issue_B(0);
    CP_COMMIT();

    float bestv[4] = {CUDART_INF_F, CUDART_INF_F, CUDART_INF_F, CUDART_INF_F};
    int   bestk[4] = {0, 0, 0, 0};

    for (int kt = 0; kt < NKT; ++kt) {
        float c[2][4][4];
#pragma unroll
        for (int mt = 0; mt < 2; ++mt)
#pragma unroll
            for (int nt = 0; nt < 4; ++nt)
#pragma unroll
                for (int q = 0; q < 4; ++q) c[mt][nt][q] = 0.f;

        for (int dc = 0; dc < NDC; ++dc) {
            const int g = kt * NDC + dc;
            if (g + 1 < NG) { issue_B(g + 1); CP_COMMIT(); CP_WAIT1(); }
            else            { CP_WAIT0(); }
            __syncthreads();                       // buf g ready for all

            const int bhi = BBUF + (g & 1) * BUFSZ;
            const int blo = bhi + DC * SB;

#pragma unroll
            for (int s8 = 0; s8 < 4; ++s8) {
                const int dd = s8 * 8 + l4;        // d within chunk
                const int da = dc * DC + dd;       // d within full A
                uint32_t ah[2][4], al[2][4];
#pragma unroll
                for (int mt = 0; mt < 2; ++mt) {
                    const int o = wo * 32 + mt * 16 + lr;
                    ah[mt][0] = __float_as_uint(sm[AHI + o * SA + da]);
                    ah[mt][1] = __float_as_uint(sm[AHI + (o + 8) * SA + da]);
                    ah[mt][2] = __float_as_uint(sm[AHI + o * SA + da + 4]);
                    ah[mt][3] = __float_as_uint(sm[AHI + (o + 8) * SA + da + 4]);
                    al[mt][0] = __float_as_uint(sm[ALO + o * SA + da]);
                    al[mt][1] = __float_as_uint(sm[ALO + (o + 8) * SA + da]);
                    al[mt][2] = __float_as_uint(sm[ALO + o * SA + da + 4]);
                    al[mt][3] = __float_as_uint(sm[ALO + (o + 8) * SA + da + 4]);
                }
                uint32_t bh[4][2], bl[4][2];
#pragma unroll
                for (int nt = 0; nt < 4; ++nt) {
                    const int n = wk * 32 + nt * 8 + lr;
                    bh[nt][0] = __float_as_uint(sm[bhi + dd * SB + n]);
                    bh[nt][1] = __float_as_uint(sm[bhi + (dd + 4) * SB + n]);
                    bl[nt][0] = __float_as_uint(sm[blo + dd * SB + n]);
                    bl[nt][1] = __float_as_uint(sm[blo + (dd + 4) * SB + n]);
                }
#pragma unroll
                for (int mt = 0; mt < 2; ++mt)
#pragma unroll
                    for (int nt = 0; nt < 4; ++nt) {
                        MMA(c[mt][nt], ah[mt], bh[nt]);   // hi*hi
                        MMA(c[mt][nt], al[mt], bh[nt]);   // lo*hi
                        MMA(c[mt][nt], ah[mt], bl[nt]);   // hi*lo
                    }
            }
            __syncthreads();                       // frag reads done before buf reuse
        }

        // ---- running argmin over this k-tile (k strictly ascending per thread)
#pragma unroll
        for (int nt = 0; nt < 4; ++nt)
#pragma unroll
            for (int q = 0; q < 2; ++q) {
                const int k = kt * KT + wk * 32 + nt * 8 + 2 * l4 + q;
                const float e2v = __ldg(&g_e2[k]);
#pragma unroll
                for (int mt = 0; mt < 2; ++mt) {
                    float v0 = fmaf(-2.f, c[mt][nt][q], e2v);       // row lr
                    if (v0 < bestv[mt * 2])     { bestv[mt * 2] = v0;     bestk[mt * 2] = k; }
                    float v1 = fmaf(-2.f, c[mt][nt][2 + q], e2v);   // row lr+8
                    if (v1 < bestv[mt * 2 + 1]) { bestv[mt * 2 + 1] = v1; bestk[mt * 2 + 1] = k; }
                }
            }
    }

    // ---- reduce across the 4 lanes of each quad (same o rows, different k)
#pragma unroll
    for (int i = 0; i < 4; ++i) {
        float v = bestv[i];
        int   k = bestk[i];
#pragma unroll
        for (int off = 1; off <= 2; off <<= 1) {
            float ov = __shfl_xor_sync(0xFFFFFFFFu, v, off);
            int   ok = __shfl_xor_sync(0xFFFFFFFFu, k, off);
            if (ov < v || (ov == v && ok < k)) { v = ov; k = ok; }
        }
        if (l4 == 0) {
            const int o = wo * 32 + (i >> 1) * 16 + (i & 1) * 8 + lr;
            sm[REDV + wk * OT + o] = v;
            reinterpret_cast<int*>(sm + REDK)[wk * OT + o] = k;
        }
    }
    __syncthreads();

    // ---- combine 4 k-warps (wk ascending = k ascending: strict < keeps first)
    int* ksarr = reinterpret_cast<int*>(sm + KSO);
    if (tid < OT) {
        float v = sm[REDV + tid];
        int   k = reinterpret_cast<int*>(sm + REDK)[tid];
#pragma unroll
        for (int w = 1; w < 4; ++w) {
            float ov = sm[REDV + w * OT + tid];
            int   ok = reinterpret_cast<int*>(sm + REDK)[w * OT + tid];
            if (ov < v) { v = ov; k = ok; }
        }
        ksarr[tid] = k;
        if (argout) argout[b * OO + o0 + tid] = (float)k;
    }
    __syncthreads();

    // ---- gather quant[b,d,o] = emb[d, ks[o]]
    if (quant) {
        float* qb = quant + (size_t)b * DD * OO + o0;
        for (int idx = tid; idx < DD * OT; idx += NT) {
            int d = idx >> 6;
            int o = idx & (OT - 1);
            qb[d * OO + o] = emb[d * KK + ksarr[o]];
        }
    }
}

// ---------------------------------------------------------------------------
extern "C" void kernel_launch(void* const* d_in, const int* in_sizes, int n_in,
                              void* d_out, int out_size) {
    const float* x   = (const float*)d_in[0];
    const float* emb = (const float*)d_in[1];
    float* out = (float*)d_out;

    const int QN = BB * DD * OO;
    const int AN = BB * OO;

    float* quant  = nullptr;
    float* argout = nullptr;
    if (out_size >= QN) {
        quant = out;
        if (out_size >= QN + AN) argout = out + QN;
    } else if (out_size >= AN) {
        argout = out;
    }

    cudaFuncSetAttribute(vq_tc, cudaFuncAttributeMaxDynamicSharedMemorySize, SM_BYTES);

    e2_kernel<<<KK / 256, 256>>>(emb);
    split_emb_kernel<<<DD * KK / 4 / 256, 256>>>(emb);

    dim3 grid(OO / OT, BB);
    vq_tc<<<grid, NT, SM_BYTES>>>(x, emb, quant, argout);
}

// round 10
// speedup vs baseline: 1.1151x; 1.1151x over previous
#include <cuda_runtime.h>
#include <math_constants.h>
#include <cstdint>

#define BB 64
#define DD 256
#define OO 1024
#define KK 1024

#define OT  64               // o-tile per CTA
#define KT  128              // k-tile per outer iteration
#define NKT (KK / KT)        // 8
#define DC  16               // d per staged chunk
#define NDC (DD / DC)        // 16
#define NG  (NKT * NDC)      // 128 pipeline iterations
#define NT  256              // 8 warps: 2 (o) x 4 (k)

#define SAS 72               // A d-row stride (floats): [d][o] padded
#define SBS 136              // B d-row stride (floats): [d][k] padded

// smem layout (floats)
#define ABUF   0
#define ABUFSZ (2 * DC * SAS)          // 2304 (hi+lo)
#define BBUF   (ABUF + 2 * ABUFSZ)     // 4608
#define BBUFSZ (2 * DC * SBS)          // 4352 (hi+lo)
#define REDV   (BBUF + 2 * BBUFSZ)     // 13312: [4][64] float
#define REDK   (REDV + 256)
#define KSO    (REDK + 256)
#define SM_FLOATS (KSO + 64)           // 13888
#define SM_BYTES  (SM_FLOATS * 4)      // 55552 -> 2 CTAs/SM

// Prep scratch: ||e||^2 + pre-split tf32 hi/lo copies of emb and x.
__device__ float g_e2[KK];
__device__ float g_ehi[DD * KK];
__device__ float g_elo[DD * KK];
__device__ float g_xhi[BB * DD * OO];
__device__ float g_xlo[BB * DD * OO];

// m16n8k8 tf32 MMA (sm_80+ encoding -> compiles on plain sm_100).
#define MMA(c, a, b)                                                          \
    asm volatile(                                                             \
        "mma.sync.aligned.m16n8k8.row.col.f32.tf32.tf32.f32 "                 \
        "{%0,%1,%2,%3}, {%4,%5,%6,%7}, {%8,%9}, {%0,%1,%2,%3};"               \
        : "+f"((c)[0]), "+f"((c)[1]), "+f"((c)[2]), "+f"((c)[3])              \
        : "r"((a)[0]), "r"((a)[1]), "r"((a)[2]), "r"((a)[3]),                 \
          "r"((b)[0]), "r"((b)[1]))

#define CP16(s, g)                                                            \
    asm volatile("cp.async.cg.shared.global [%0], [%1], 16;"                  \
        :: "r"(s), "l"((unsigned long long)__cvta_generic_to_global((const void*)(g))))
#define CP_COMMIT() asm volatile("cp.async.commit_group;" ::: "memory")
#define CP_WAIT1()  asm volatile("cp.async.wait_group 1;" ::: "memory")
#define CP_WAIT0()  asm volatile("cp.async.wait_group 0;" ::: "memory")

__device__ __forceinline__ uint32_t smem_u32(const void* p) {
    uint32_t a;
    asm("{ .reg .u64 t; cvta.to.shared.u64 t, %1; cvt.u32.u64 %0, t; }" : "=r"(a) : "l"(p));
    return a;
}

__device__ __forceinline__ void tf32_split(float v, float& hi, float& lo) {
    uint32_t h;
    asm("cvt.rna.tf32.f32 %0, %1;" : "=r"(h) : "f"(v));
    hi = __uint_as_float(h);
    float r = v - hi;
    uint32_t l;
    asm("cvt.rna.tf32.f32 %0, %1;" : "=r"(l) : "f"(r));
    lo = __uint_as_float(l);
}

// ---------------------------------------------------------------------------
// Prep kernels
// ---------------------------------------------------------------------------
__global__ void e2_kernel(const float* __restrict__ emb) {   // grid 32 x 256
    __shared__ float red[8][32];
    const int k  = blockIdx.x * 32 + (threadIdx.x & 31);
    const int dg = threadIdx.x >> 5;
    float s = 0.f;
#pragma unroll
    for (int d = dg * 32; d < dg * 32 + 32; ++d) {
        float v = emb[d * KK + k];
        s = fmaf(v, v, s);
    }
    red[dg][threadIdx.x & 31] = s;
    __syncthreads();
    if (dg == 0) {
        float t = 0.f;
#pragma unroll
        for (int i = 0; i < 8; ++i) t += red[i][threadIdx.x & 31];
        g_e2[k] = t;
    }
}

__global__ void split_emb_kernel(const float* __restrict__ emb) {
    int i = blockIdx.x * blockDim.x + threadIdx.x;           // DD*KK/4 float4
    float4 v = reinterpret_cast<const float4*>(emb)[i];
    float h0, l0, h1, l1, h2, l2, h3, l3;
    tf32_split(v.x, h0, l0); tf32_split(v.y, h1, l1);
    tf32_split(v.z, h2, l2); tf32_split(v.w, h3, l3);
    reinterpret_cast<float4*>(g_ehi)[i] = make_float4(h0, h1, h2, h3);
    reinterpret_cast<float4*>(g_elo)[i] = make_float4(l0, l1, l2, l3);
}

__global__ void split_x_kernel(const float* __restrict__ x) {
    size_t i = (size_t)blockIdx.x * blockDim.x + threadIdx.x; // BB*DD*OO/4 float4
    float4 v = reinterpret_cast<const float4*>(x)[i];
    float h0, l0, h1, l1, h2, l2, h3, l3;
    tf32_split(v.x, h0, l0); tf32_split(v.y, h1, l1);
    tf32_split(v.z, h2, l2); tf32_split(v.w, h3, l3);
    reinterpret_cast<float4*>(g_xhi)[i] = make_float4(h0, h1, h2, h3);
    reinterpret_cast<float4*>(g_xlo)[i] = make_float4(l0, l1, l2, l3);
}

// ---------------------------------------------------------------------------
// Fused 3xTF32 mma.sync GEMM + running argmin + gather.
// CTA: one b x 64 o. A and B streamed from pre-split globals via
// double-buffered cp.async; zero cvt / zero register staging in the hot loop.
// ---------------------------------------------------------------------------
extern __shared__ float sm[];

__global__ __launch_bounds__(NT, 2)
void vq_tc(const float* __restrict__ emb,
           float* __restrict__ quant, float* __restrict__ argout) {
    const int tid  = threadIdx.x;
    const int lane = tid & 31;
    const int wid  = tid >> 5;
    const int wo   = wid & 1;       // o half
    const int wk   = wid >> 1;      // k quarter
    const int b    = blockIdx.y;
    const int o0   = blockIdx.x * OT;
    const int l4   = lane & 3;
    const int lr   = lane >> 2;

    const uint32_t sb = smem_u32(sm);

    // cp.async stage for pipeline iteration g (kt = g>>4, dc = g&15, buf = g&1).
    auto issue = [&](int g) {
        const int ktn = g >> 4, dcn = g & 15, buf = g & 1;
        const int d0 = dcn * DC;
        // A: 512 16B chunks (hi 256 + lo 256): [d][o] rows of 64 floats
#pragma unroll
        for (int it = 0; it < 2; ++it) {
            int c = tid + it * NT;
            int hl = c >> 8, rem = c & 255;
            int d = rem >> 4, o4 = rem & 15;
            const float* src = (hl ? g_xlo : g_xhi)
                + (size_t)b * DD * OO + (size_t)(d0 + d) * OO + o0 + o4 * 4;
            uint32_t dst = sb + (ABUF + buf * ABUFSZ + hl * (DC * SAS)
                                 + d * SAS + o4 * 4) * 4;
            CP16(dst, src);
        }
        // B: 1024 16B chunks (hi 512 + lo 512): [d][k] rows of 128 floats
#pragma unroll
        for (int it = 0; it < 4; ++it) {
            int c = tid + it * NT;
            int hl = c >> 9, rem = c & 511;
            int d = rem >> 5, k4 = rem & 31;
            const float* src = (hl ? g_elo : g_ehi)
                + (size_t)(d0 + d) * KK + ktn * KT + k4 * 4;
            uint32_t dst = sb + (BBUF + buf * BBUFSZ + hl * (DC * SBS)
                                 + d * SBS + k4 * 4) * 4;
            CP16(dst, src);
        }
    };

    issue(0);
    CP_COMMIT();

    float bestv[4] = {CUDART_INF_F, CUDART_INF_F, CUDART_INF_F, CUDART_INF_F};
    int   bestk[4] = {0, 0, 0, 0};

    for (int kt = 0; kt < NKT; ++kt) {
        float c[2][4][4];
#pragma unroll
        for (int mt = 0; mt < 2; ++mt)
#pragma unroll
            for (int nt = 0; nt < 4; ++nt)
#pragma unroll
                for (int q = 0; q < 4; ++q) c[mt][nt][q] = 0.f;

        for (int dc = 0; dc < NDC; ++dc) {
            const int g = kt * NDC + dc;
            if (g + 1 < NG) { issue(g + 1); CP_COMMIT(); CP_WAIT1(); }
            else            { CP_WAIT0(); }
            __syncthreads();                       // buf g ready for all

            const int ahi = ABUF + (g & 1) * ABUFSZ;
            const int alo = ahi + DC * SAS;
            const int bhi = BBUF + (g & 1) * BBUFSZ;
            const int blo = bhi + DC * SBS;

#pragma unroll
            for (int s8 = 0; s8 < 2; ++s8) {
                const int dd = s8 * 8 + l4;
                uint32_t ah[2][4], al[2][4];
#pragma unroll
                for (int mt = 0; mt < 2; ++mt) {
                    const int o = wo * 32 + mt * 16 + lr;
                    ah[mt][0] = __float_as_uint(sm[ahi + dd * SAS + o]);
                    ah[mt][1] = __float_as_uint(sm[ahi + dd * SAS + o + 8]);
                    ah[mt][2] = __float_as_uint(sm[ahi + (dd + 4) * SAS + o]);
                    ah[mt][3] = __float_as_uint(sm[ahi + (dd + 4) * SAS + o + 8]);
                    al[mt][0] = __float_as_uint(sm[alo + dd * SAS + o]);
                    al[mt][1] = __float_as_uint(sm[alo + dd * SAS + o + 8]);
                    al[mt][2] = __float_as_uint(sm[alo + (dd + 4) * SAS + o]);
                    al[mt][3] = __float_as_uint(sm[alo + (dd + 4) * SAS + o + 8]);
                }
                uint32_t bh[4][2], bl[4][2];
#pragma unroll
                for (int nt = 0; nt < 4; ++nt) {
                    const int n = wk * 32 + nt * 8 + lr;
                    bh[nt][0] = __float_as_uint(sm[bhi + dd * SBS + n]);
                    bh[nt][1] = __float_as_uint(sm[bhi + (dd + 4) * SBS + n]);
                    bl[nt][0] = __float_as_uint(sm[blo + dd * SBS + n]);
                    bl[nt][1] = __float_as_uint(sm[blo + (dd + 4) * SBS + n]);
                }
#pragma unroll
                for (int mt = 0; mt < 2; ++mt)
#pragma unroll
                    for (int nt = 0; nt < 4; ++nt) {
                        MMA(c[mt][nt], ah[mt], bh[nt]);   // hi*hi
                        MMA(c[mt][nt], al[mt], bh[nt]);   // lo*hi
                        MMA(c[mt][nt], ah[mt], bl[nt]);   // hi*lo
                    }
            }
            __syncthreads();                       // frag reads done before buf reuse
        }

        // ---- running argmin over this k-tile (k strictly ascending per thread)
#pragma unroll
        for (int nt = 0; nt < 4; ++nt)
#pragma unroll
            for (int q = 0; q < 2; ++q) {
                const int k = kt * KT + wk * 32 + nt * 8 + 2 * l4 + q;
                const float e2v = __ldg(&g_e2[k]);
#pragma unroll
                for (int mt = 0; mt < 2; ++mt) {
                    float v0 = fmaf(-2.f, c[mt][nt][q], e2v);       // row lr
                    if (v0 < bestv[mt * 2])     { bestv[mt * 2] = v0;     bestk[mt * 2] = k; }
                    float v1 = fmaf(-2.f, c[mt][nt][2 + q], e2v);   // row lr+8
                    if (v1 < bestv[mt * 2 + 1]) { bestv[mt * 2 + 1] = v1; bestk[mt * 2 + 1] = k; }
                }
            }
    }

    // ---- reduce across the 4 lanes of each quad (same o rows, different k)
#pragma unroll
    for (int i = 0; i < 4; ++i) {
        float v = bestv[i];
        int   k = bestk[i];
#pragma unroll
        for (int off = 1; off <= 2; off <<= 1) {
            float ov = __shfl_xor_sync(0xFFFFFFFFu, v, off);
            int   ok = __shfl_xor_sync(0xFFFFFFFFu, k, off);
            if (ov < v || (ov == v && ok < k)) { v = ov; k = ok; }
        }
        if (l4 == 0) {
            const int o = wo * 32 + (i >> 1) * 16 + (i & 1) * 8 + lr;
            sm[REDV + wk * OT + o] = v;
            reinterpret_cast<int*>(sm + REDK)[wk * OT + o] = k;
        }
    }
    __syncthreads();

    // ---- combine 4 k-warps (wk ascending = k ascending: strict < keeps first)
    int* ksarr = reinterpret_cast<int*>(sm + KSO);
    if (tid < OT) {
        float v = sm[REDV + tid];
        int   k = reinterpret_cast<int*>(sm + REDK)[tid];
#pragma unroll
        for (int w = 1; w < 4; ++w) {
            float ov = sm[REDV + w * OT + tid];
            int   ok = reinterpret_cast<int*>(sm + REDK)[w * OT + tid];
            if (ov < v) { v = ov; k = ok; }
        }
        ksarr[tid] = k;
        if (argout) argout[b * OO + o0 + tid] = (float)k;
    }
    __syncthreads();

    // ---- gather quant[b,d,o] = emb[d, ks[o]]
    if (quant) {
        float* qb = quant + (size_t)b * DD * OO + o0;
        for (int idx = tid; idx < DD * OT; idx += NT) {
            int d = idx >> 6;
            int o = idx & (OT - 1);
            qb[d * OO + o] = emb[d * KK + ksarr[o]];
        }
    }
}

// ---------------------------------------------------------------------------
extern "C" void kernel_launch(void* const* d_in, const int* in_sizes, int n_in,
                              void* d_out, int out_size) {
    const float* x   = (const float*)d_in[0];
    const float* emb = (const float*)d_in[1];
    float* out = (float*)d_out;

    const int QN = BB * DD * OO;
    const int AN = BB * OO;

    float* quant  = nullptr;
    float* argout = nullptr;
    if (out_size >= QN) {
        quant = out;
        if (out_size >= QN + AN) argout = out + QN;
    } else if (out_size >= AN) {
        argout = out;
    }

    cudaFuncSetAttribute(vq_tc, cudaFuncAttributeMaxDynamicSharedMemorySize, SM_BYTES);

    e2_kernel<<<KK / 32, 256>>>(emb);
    split_emb_kernel<<<DD * KK / 4 / 256, 256>>>(emb);
    split_x_kernel<<<BB * DD * OO / 4 / 256, 256>>>(x);

    dim3 grid(OO / OT, BB);
    vq_tc<<<grid, NT, SM_BYTES>>>(emb, quant, argout);
}

// round 11
// speedup vs baseline: 1.4922x; 1.3382x over previous
#include <cuda_runtime.h>
#include <cuda_fp16.h>
#include <math_constants.h>
#include <cstdint>

#define BB 64
#define DD 256
#define OO 1024
#define KK 1024

#define OT  64               // o-tile per CTA
#define KT  128              // k-tile per outer iteration
#define NKT (KK / KT)        // 8
#define DC  16               // d per staged chunk (one m16n8k16 K step)
#define NDC (DD / DC)        // 16
#define NG  (NKT * NDC)      // 128 pipeline iterations
#define NT  256              // 8 warps: 2 (o) x 4 (k)
#define NBUF 4

// smem layout in 32-bit words
#define BUFW  3072           // per buffer: Ahi 512 | Alo 512 | Bhi 1024 | Blo 1024
#define AHIW  0
#define ALOW  512
#define BHIW  1024
#define REDVW (NBUF * BUFW)  // 12288: [4][64] float
#define REDKW (REDVW + 256)
#define KSOW  (REDKW + 256)
#define SM_WORDS (KSOW + 64) // 12864
#define SM_BYTES (SM_WORDS * 4)   // 51456 -> 2 CTAs/SM

// Prep scratch: ||e||^2 + fp16 hi/lo SPLIT+TRANSPOSED copies.
__device__ float  g_e2[KK];
__device__ __half g_ehT[KK * DD];                // [k][d]
__device__ __half g_elT[KK * DD];
__device__ __half g_xhT[(size_t)BB * OO * DD];   // [b][o][d]
__device__ __half g_xlT[(size_t)BB * OO * DD];

// m16n8k16 fp16 MMA, fp32 accumulate (sm_80+ -> compiles on plain sm_100).
#define MMA(c, a, b)                                                          \
    asm volatile(                                                             \
        "mma.sync.aligned.m16n8k16.row.col.f32.f16.f16.f32 "                  \
        "{%0,%1,%2,%3}, {%4,%5,%6,%7}, {%8,%9}, {%0,%1,%2,%3};"               \
        : "+f"((c)[0]), "+f"((c)[1]), "+f"((c)[2]), "+f"((c)[3])              \
        : "r"((a)[0]), "r"((a)[1]), "r"((a)[2]), "r"((a)[3]),                 \
          "r"((b)[0]), "r"((b)[1]))

#define CP16(s, g)                                                            \
    asm volatile("cp.async.cg.shared.global [%0], [%1], 16;"                  \
        :: "r"(s), "l"((unsigned long long)__cvta_generic_to_global((const void*)(g))))
#define CP_COMMIT() asm volatile("cp.async.commit_group;" ::: "memory")
#define CP_WAIT2()  asm volatile("cp.async.wait_group 2;" ::: "memory")
#define CP_WAIT0()  asm volatile("cp.async.wait_group 0;" ::: "memory")

__device__ __forceinline__ uint32_t smem_u32(const void* p) {
    uint32_t a;
    asm("{ .reg .u64 t; cvta.to.shared.u64 t, %1; cvt.u32.u64 %0, t; }" : "=r"(a) : "l"(p));
    return a;
}

__device__ __forceinline__ void h_split(float v, __half& h, __half& l) {
    h = __float2half_rn(v);
    l = __float2half_rn(v - __half2float(h));
}

// ---------------------------------------------------------------------------
// Prep kernels
// ---------------------------------------------------------------------------
__global__ void e2_kernel(const float* __restrict__ emb) {   // grid 32 x 256
    __shared__ float red[8][32];
    const int k  = blockIdx.x * 32 + (threadIdx.x & 31);
    const int dg = threadIdx.x >> 5;
    float s = 0.f;
#pragma unroll
    for (int d = dg * 32; d < dg * 32 + 32; ++d) {
        float v = emb[d * KK + k];
        s = fmaf(v, v, s);
    }
    red[dg][threadIdx.x & 31] = s;
    __syncthreads();
    if (dg == 0) {
        float t = 0.f;
#pragma unroll
        for (int i = 0; i < 8; ++i) t += red[i][threadIdx.x & 31];
        g_e2[k] = t;
    }
}

// emb [d][k] f32 -> g_e{h,l}T [k][d] fp16.  grid (KK/32, DD/32) x 256.
__global__ void splitT_emb(const float* __restrict__ emb) {
    __shared__ float tile[32][33];
    const int tx = threadIdx.x & 31, ty = threadIdx.x >> 5;
    const int k0t = blockIdx.x * 32, d0t = blockIdx.y * 32;
#pragma unroll
    for (int i = 0; i < 4; ++i) {
        int d = ty + i * 8;
        tile[d][tx] = emb[(d0t + d) * KK + k0t + tx];     // coalesced over k
    }
    __syncthreads();
#pragma unroll
    for (int i = 0; i < 4; ++i) {
        int k = ty + i * 8;
        float v = tile[tx][k];                            // d = tx
        __half h, l; h_split(v, h, l);
        g_ehT[(size_t)(k0t + k) * DD + d0t + tx] = h;     // coalesced over d
        g_elT[(size_t)(k0t + k) * DD + d0t + tx] = l;
    }
}

// x [b][d][o] f32 -> g_x{h,l}T [b][o][d] fp16.  grid (OO/32, DD/32, BB) x 256.
__global__ void splitT_x(const float* __restrict__ x) {
    __shared__ float tile[32][33];
    const int tx = threadIdx.x & 31, ty = threadIdx.x >> 5;
    const int o0t = blockIdx.x * 32, d0t = blockIdx.y * 32;
    const int b = blockIdx.z;
    const float* src = x + ((size_t)b * DD + d0t) * OO + o0t;
#pragma unroll
    for (int i = 0; i < 4; ++i) {
        int d = ty + i * 8;
        tile[d][tx] = src[d * OO + tx];                   // coalesced over o
    }
    __syncthreads();
    __half* dh = g_xhT + ((size_t)b * OO + o0t) * DD + d0t;
    __half* dl = g_xlT + ((size_t)b * OO + o0t) * DD + d0t;
#pragma unroll
    for (int i = 0; i < 4; ++i) {
        int o = ty + i * 8;
        float v = tile[tx][o];                            // d = tx
        __half h, l; h_split(v, h, l);
        dh[(size_t)o * DD + tx] = h;                      // coalesced over d
        dl[(size_t)o * DD + tx] = l;
    }
}

// ---------------------------------------------------------------------------
// Fused 3xFP16-split mma.sync GEMM + running argmin + gather.
// CTA: one b x 64 o. 4-buffer cp.async pipeline, 1 barrier per dc iteration.
// Smem tiles use a 16B-chunk XOR swizzle (chunk ^= (row>>2)&1) so all
// fragment LDS are bank-conflict-free.
// ---------------------------------------------------------------------------
extern __shared__ uint32_t smw[];

__global__ __launch_bounds__(NT, 2)
void vq_tc(const float* __restrict__ emb,
           float* __restrict__ quant, float* __restrict__ argout) {
    const int tid  = threadIdx.x;
    const int lane = tid & 31;
    const int wid  = tid >> 5;
    const int wo   = wid & 1;       // o half
    const int wk   = wid >> 1;      // k quarter
    const int b    = blockIdx.y;
    const int o0   = blockIdx.x * OT;
    const int l4   = lane & 3;
    const int lr   = lane >> 2;

    const uint32_t sb = smem_u32(smw);
    float* smf = reinterpret_cast<float*>(smw);

    // cp.async stage for pipeline iteration g2 into buffer g2&3.
    auto issue = [&](int g2) {
        const int ktn = g2 >> 4, d0 = (g2 & 15) * DC;
        const uint32_t bw = (uint32_t)(g2 & 3) * BUFW;
        {   // A: 256 chunks (hi 128 + lo 128): 64 o-rows x 2 chunks
            int hl = tid >> 7, o = (tid >> 1) & 63, c = tid & 1;
            const __half* src = (hl ? g_xlT : g_xhT)
                + ((size_t)b * OO + o0 + o) * DD + d0 + c * 8;
            uint32_t dst = sb + (bw + AHIW + hl * 512 + o * 8
                                 + ((c ^ ((o >> 2) & 1)) << 2)) * 4;
            CP16(dst, src);
        }
#pragma unroll
        for (int it = 0; it < 2; ++it) {   // B: 512 chunks: 128 k-rows x 2 x hl
            int idx = tid + it * NT;
            int hl = idx >> 8, k = (idx >> 1) & 127, c = idx & 1;
            const __half* src = (hl ? g_elT : g_ehT)
                + (size_t)(ktn * KT + k) * DD + d0 + c * 8;
            uint32_t dst = sb + (bw + BHIW + hl * 1024 + k * 8
                                 + ((c ^ ((k >> 2) & 1)) << 2)) * 4;
            CP16(dst, src);
        }
    };

    issue(0); CP_COMMIT();
    issue(1); CP_COMMIT();
    issue(2); CP_COMMIT();

    float bestv[4] = {CUDART_INF_F, CUDART_INF_F, CUDART_INF_F, CUDART_INF_F};
    int   bestk[4] = {0, 0, 0, 0};

    for (int kt = 0; kt < NKT; ++kt) {
        float c[2][4][4];
#pragma unroll
        for (int mt = 0; mt < 2; ++mt)
#pragma unroll
            for (int nt = 0; nt < 4; ++nt)
#pragma unroll
                for (int q = 0; q < 4; ++q) c[mt][nt][q] = 0.f;

        for (int dc = 0; dc < NDC; ++dc) {
            const int g = kt * NDC + dc;
            if (g + 2 < NG) CP_WAIT2(); else CP_WAIT0();
            __syncthreads();                 // buf g visible; MMA(g-1) done by all
            if (g + 3 < NG) { issue(g + 3); CP_COMMIT(); }

            const uint32_t* bw = smw + (g & 3) * BUFW;

            // ---- A fragments (rows o, cols d): swizzled chunk addressing
            uint32_t ah[2][4], al[2][4];
#pragma unroll
            for (int mt = 0; mt < 2; ++mt) {
                const int oa = wo * 32 + mt * 16 + lr;
                const int ob = oa + 8;
                const int sa = (oa >> 2) & 1, sc = (ob >> 2) & 1;
                ah[mt][0] = bw[AHIW + oa * 8 + (sa << 2) + l4];
                ah[mt][1] = bw[AHIW + ob * 8 + (sc << 2) + l4];
                ah[mt][2] = bw[AHIW + oa * 8 + ((1 ^ sa) << 2) + l4];
                ah[mt][3] = bw[AHIW + ob * 8 + ((1 ^ sc) << 2) + l4];
                al[mt][0] = bw[ALOW + oa * 8 + (sa << 2) + l4];
                al[mt][1] = bw[ALOW + ob * 8 + (sc << 2) + l4];
                al[mt][2] = bw[ALOW + oa * 8 + ((1 ^ sa) << 2) + l4];
                al[mt][3] = bw[ALOW + ob * 8 + ((1 ^ sc) << 2) + l4];
            }
            // ---- B fragments (rows k_code, cols d)
            uint32_t bh[4][2], bl[4][2];
#pragma unroll
            for (int nt = 0; nt < 4; ++nt) {
                const int n = wk * 32 + nt * 8 + lr;
                const int sn = (n >> 2) & 1;
                bh[nt][0] = bw[BHIW + n * 8 + (sn << 2) + l4];
                bh[nt][1] = bw[BHIW + n * 8 + ((1 ^ sn) << 2) + l4];
                bl[nt][0] = bw[BHIW + 1024 + n * 8 + (sn << 2) + l4];
                bl[nt][1] = bw[BHIW + 1024 + n * 8 + ((1 ^ sn) << 2) + l4];
            }
#pragma unroll
            for (int mt = 0; mt < 2; ++mt)
#pragma unroll
                for (int nt = 0; nt < 4; ++nt) {
                    MMA(c[mt][nt], ah[mt], bh[nt]);   // hi*hi
                    MMA(c[mt][nt], al[mt], bh[nt]);   // lo*hi
                    MMA(c[mt][nt], ah[mt], bl[nt]);   // hi*lo
                }
        }

        // ---- running argmin over this k-tile (k strictly ascending per thread)
#pragma unroll
        for (int nt = 0; nt < 4; ++nt)
#pragma unroll
            for (int q = 0; q < 2; ++q) {
                const int k = kt * KT + wk * 32 + nt * 8 + 2 * l4 + q;
                const float e2v = __ldg(&g_e2[k]);
#pragma unroll
                for (int mt = 0; mt < 2; ++mt) {
                    float v0 = fmaf(-2.f, c[mt][nt][q], e2v);       // row lr
                    if (v0 < bestv[mt * 2])     { bestv[mt * 2] = v0;     bestk[mt * 2] = k; }
                    float v1 = fmaf(-2.f, c[mt][nt][2 + q], e2v);   // row lr+8
                    if (v1 < bestv[mt * 2 + 1]) { bestv[mt * 2 + 1] = v1; bestk[mt * 2 + 1] = k; }
                }
            }
    }

    // ---- reduce across the 4 lanes of each quad (same o rows, different k)
#pragma unroll
    for (int i = 0; i < 4; ++i) {
        float v = bestv[i];
        int   k = bestk[i];
#pragma unroll
        for (int off = 1; off <= 2; off <<= 1) {
            float ov = __shfl_xor_sync(0xFFFFFFFFu, v, off);
            int   ok = __shfl_xor_sync(0xFFFFFFFFu, k, off);
            if (ov < v || (ov == v && ok < k)) { v = ov; k = ok; }
        }
        if (l4 == 0) {
            const int o = wo * 32 + (i >> 1) * 16 + (i & 1) * 8 + lr;
            smf[REDVW + wk * OT + o] = v;
            reinterpret_cast<int*>(smw)[REDKW + wk * OT + o] = k;
        }
    }
    __syncthreads();

    // ---- combine 4 k-warps (wk ascending = k ascending: strict < keeps first)
    int* ksarr = reinterpret_cast<int*>(smw) + KSOW;
    if (tid < OT) {
        float v = smf[REDVW + tid];
        int   k = reinterpret_cast<int*>(smw)[REDKW + tid];
#pragma unroll
        for (int w = 1; w < 4; ++w) {
            float ov = smf[REDVW + w * OT + tid];
            int   ok = reinterpret_cast<int*>(smw)[REDKW + w * OT + tid];
            if (ov < v) { v = ov; k = ok; }
        }
        ksarr[tid] = k;
        if (argout) argout[b * OO + o0 + tid] = (float)k;
    }
    __syncthreads();

    // ---- gather quant[b,d,o] = emb[d, ks[o]]
    if (quant) {
        float* qb = quant + (size_t)b * DD * OO + o0;
        for (int idx = tid; idx < DD * OT; idx += NT) {
            int d = idx >> 6;
            int o = idx & (OT - 1);
            qb[d * OO + o] = emb[d * KK + ksarr[o]];
        }
    }
}

// ---------------------------------------------------------------------------
extern "C" void kernel_launch(void* const* d_in, const int* in_sizes, int n_in,
                              void* d_out, int out_size) {
    const float* x   = (const float*)d_in[0];
    const float* emb = (const float*)d_in[1];
    float* out = (float*)d_out;

    const int QN = BB * DD * OO;
    const int AN = BB * OO;

    float* quant  = nullptr;
    float* argout = nullptr;
    if (out_size >= QN) {
        quant = out;
        if (out_size >= QN + AN) argout = out + QN;
    } else if (out_size >= AN) {
        argout = out;
    }

    cudaFuncSetAttribute(vq_tc, cudaFuncAttributeMaxDynamicSharedMemorySize, SM_BYTES);

    e2_kernel<<<KK / 32, 256>>>(emb);
    splitT_emb<<<dim3(KK / 32, DD / 32), 256>>>(emb);
    splitT_x<<<dim3(OO / 32, DD / 32, BB), 256>>>(x);

    dim3 grid(OO / OT, BB);
    vq_tc<<<grid, NT, SM_BYTES>>>(emb, quant, argout);
}

// round 12
// speedup vs baseline: 1.5156x; 1.0157x over previous
#include <cuda_runtime.h>
#include <cuda_fp16.h>
#include <math_constants.h>
#include <cstdint>

#define BB 64
#define DD 256
#define OO 1024
#define KK 1024

#define OT  128              // o-tile per CTA
#define KT  128              // k-tile per outer iteration
#define NKT (KK / KT)        // 8
#define DC  16               // d per staged chunk (one m16n8k16 K step)
#define NDC (DD / DC)        // 16
#define NG  (NKT * NDC)      // 128 pipeline iterations
#define NT  256              // 8 warps: 4 (o) x 2 (k); warp tile 32o x 64k
#define NBUF 4

// smem layout in 32-bit words
#define BUFW  4096           // per buffer: Ahi 1024 | Alo 1024 | Bhi 1024 | Blo 1024
#define AHIW  0
#define BHIW  2048
#define REDVW (NBUF * BUFW)  // 16384: [2][128] float
#define REDKW (REDVW + 256)
#define KSOW  (REDKW + 256)
#define SM_WORDS (KSOW + 128) // 17024
#define SM_BYTES (SM_WORDS * 4)   // 68096 -> 2 CTAs/SM

// Prep scratch: ||e||^2 + fp16 hi/lo SPLIT+TRANSPOSED copies.
__device__ float  g_e2[KK];
__device__ __half g_ehT[KK * DD];                // [k][d]
__device__ __half g_elT[KK * DD];
__device__ __half g_xhT[(size_t)BB * OO * DD];   // [b][o][d]
__device__ __half g_xlT[(size_t)BB * OO * DD];

// m16n8k16 fp16 MMA, fp32 accumulate (sm_80+ -> compiles on plain sm_100).
#define MMA(c, a, b)                                                          \
    asm volatile(                                                             \
        "mma.sync.aligned.m16n8k16.row.col.f32.f16.f16.f32 "                  \
        "{%0,%1,%2,%3}, {%4,%5,%6,%7}, {%8,%9}, {%0,%1,%2,%3};"               \
        : "+f"((c)[0]), "+f"((c)[1]), "+f"((c)[2]), "+f"((c)[3])              \
        : "r"((a)[0]), "r"((a)[1]), "r"((a)[2]), "r"((a)[3]),                 \
          "r"((b)[0]), "r"((b)[1]))

#define CP16(s, g)                                                            \
    asm volatile("cp.async.cg.shared.global [%0], [%1], 16;"                  \
        :: "r"(s), "l"((unsigned long long)__cvta_generic_to_global((const void*)(g))))
#define CP_COMMIT() asm volatile("cp.async.commit_group;" ::: "memory")
#define CP_WAIT2()  asm volatile("cp.async.wait_group 2;" ::: "memory")
#define CP_WAIT0()  asm volatile("cp.async.wait_group 0;" ::: "memory")

__device__ __forceinline__ uint32_t smem_u32(const void* p) {
    uint32_t a;
    asm("{ .reg .u64 t; cvta.to.shared.u64 t, %1; cvt.u32.u64 %0, t; }" : "=r"(a) : "l"(p));
    return a;
}

__device__ __forceinline__ void h_split(float v, __half& h, __half& l) {
    h = __float2half_rn(v);
    l = __float2half_rn(v - __half2float(h));
}

// ---------------------------------------------------------------------------
// Prep kernels (unchanged from the validated R10 versions)
// ---------------------------------------------------------------------------
__global__ void e2_kernel(const float* __restrict__ emb) {   // grid 32 x 256
    __shared__ float red[8][32];
    const int k  = blockIdx.x * 32 + (threadIdx.x & 31);
    const int dg = threadIdx.x >> 5;
    float s = 0.f;
#pragma unroll
    for (int d = dg * 32; d < dg * 32 + 32; ++d) {
        float v = emb[d * KK + k];
        s = fmaf(v, v, s);
    }
    red[dg][threadIdx.x & 31] = s;
    __syncthreads();
    if (dg == 0) {
        float t = 0.f;
#pragma unroll
        for (int i = 0; i < 8; ++i) t += red[i][threadIdx.x & 31];
        g_e2[k] = t;
    }
}

__global__ void splitT_emb(const float* __restrict__ emb) {
    __shared__ float tile[32][33];
    const int tx = threadIdx.x & 31, ty = threadIdx.x >> 5;
    const int k0t = blockIdx.x * 32, d0t = blockIdx.y * 32;
#pragma unroll
    for (int i = 0; i < 4; ++i) {
        int d = ty + i * 8;
        tile[d][tx] = emb[(d0t + d) * KK + k0t + tx];
    }
    __syncthreads();
#pragma unroll
    for (int i = 0; i < 4; ++i) {
        int k = ty + i * 8;
        float v = tile[tx][k];
        __half h, l; h_split(v, h, l);
        g_ehT[(size_t)(k0t + k) * DD + d0t + tx] = h;
        g_elT[(size_t)(k0t + k) * DD + d0t + tx] = l;
    }
}

__global__ void splitT_x(const float* __restrict__ x) {
    __shared__ float tile[32][33];
    const int tx = threadIdx.x & 31, ty = threadIdx.x >> 5;
    const int o0t = blockIdx.x * 32, d0t = blockIdx.y * 32;
    const int b = blockIdx.z;
    const float* src = x + ((size_t)b * DD + d0t) * OO + o0t;
#pragma unroll
    for (int i = 0; i < 4; ++i) {
        int d = ty + i * 8;
        tile[d][tx] = src[d * OO + tx];
    }
    __syncthreads();
    __half* dh = g_xhT + ((size_t)b * OO + o0t) * DD + d0t;
    __half* dl = g_xlT + ((size_t)b * OO + o0t) * DD + d0t;
#pragma unroll
    for (int i = 0; i < 4; ++i) {
        int o = ty + i * 8;
        float v = tile[tx][o];
        __half h, l; h_split(v, h, l);
        dh[(size_t)o * DD + tx] = h;
        dl[(size_t)o * DD + tx] = l;
    }
}

// ---------------------------------------------------------------------------
// Fused 3xFP16-split mma.sync GEMM + running argmin + gather.
// CTA: one b x 128 o. Warp grid 4(o) x 2(k): warp tile 32o x 64k -> fragment
// smem traffic per output cut 25% vs the 64o tile (crossbar was binding).
// 4-buffer cp.async pipeline, 1 barrier per dc iteration, XOR-chunk swizzle.
// ---------------------------------------------------------------------------
extern __shared__ uint32_t smw[];

__global__ __launch_bounds__(NT, 2)
void vq_tc(const float* __restrict__ emb,
           float* __restrict__ quant, float* __restrict__ argout) {
    const int tid  = threadIdx.x;
    const int lane = tid & 31;
    const int wid  = tid >> 5;
    const int wo   = wid >> 1;      // o quarter (0..3)
    const int wk   = wid & 1;       // k half (0..1)
    const int b    = blockIdx.y;
    const int o0   = blockIdx.x * OT;
    const int l4   = lane & 3;
    const int lr   = lane >> 2;

    const uint32_t sb = smem_u32(smw);
    float* smf = reinterpret_cast<float*>(smw);

    // cp.async stage for pipeline iteration g2 into buffer g2&3.
    // 1024 16B chunks: A = hi/lo x 128 o-rows x 2, B = hi/lo x 128 k-rows x 2.
    auto issue = [&](int g2) {
        const int ktn = g2 >> 4, d0 = (g2 & 15) * DC;
        const uint32_t bw = (uint32_t)(g2 & 3) * BUFW;
#pragma unroll
        for (int it = 0; it < 2; ++it) {   // A chunks 0..511
            int c = tid + it * NT;
            int hl = c >> 8, o = (c >> 1) & 127, ch = c & 1;
            const __half* src = (hl ? g_xlT : g_xhT)
                + ((size_t)b * OO + o0 + o) * DD + d0 + ch * 8;
            uint32_t dst = sb + (bw + AHIW + hl * 1024 + o * 8
                                 + ((ch ^ ((o >> 2) & 1)) << 2)) * 4;
            CP16(dst, src);
        }
#pragma unroll
        for (int it = 0; it < 2; ++it) {   // B chunks 0..511
            int c = tid + it * NT;
            int hl = c >> 8, k = (c >> 1) & 127, ch = c & 1;
            const __half* src = (hl ? g_elT : g_ehT)
                + (size_t)(ktn * KT + k) * DD + d0 + ch * 8;
            uint32_t dst = sb + (bw + BHIW + hl * 1024 + k * 8
                                 + ((ch ^ ((k >> 2) & 1)) << 2)) * 4;
            CP16(dst, src);
        }
    };

    issue(0); CP_COMMIT();
    issue(1); CP_COMMIT();
    issue(2); CP_COMMIT();

    float bestv[4] = {CUDART_INF_F, CUDART_INF_F, CUDART_INF_F, CUDART_INF_F};
    int   bestk[4] = {0, 0, 0, 0};

    for (int kt = 0; kt < NKT; ++kt) {
        float c[2][8][4];
#pragma unroll
        for (int mt = 0; mt < 2; ++mt)
#pragma unroll
            for (int nt = 0; nt < 8; ++nt)
#pragma unroll
                for (int q = 0; q < 4; ++q) c[mt][nt][q] = 0.f;

        for (int dc = 0; dc < NDC; ++dc) {
            const int g = kt * NDC + dc;
            if (g + 2 < NG) CP_WAIT2(); else CP_WAIT0();
            __syncthreads();                 // buf g visible; MMA(g-1) done by all
            if (g + 3 < NG) { issue(g + 3); CP_COMMIT(); }

            const uint32_t* bw = smw + (g & 3) * BUFW;

            // ---- A fragments (rows o, cols d): swizzled chunk addressing
            uint32_t ah[2][4], al[2][4];
#pragma unroll
            for (int mt = 0; mt < 2; ++mt) {
                const int oa = wo * 32 + mt * 16 + lr;
                const int ob = oa + 8;
                const int sa = (oa >> 2) & 1, sc = (ob >> 2) & 1;
                ah[mt][0] = bw[AHIW + oa * 8 + (sa << 2) + l4];
                ah[mt][1] = bw[AHIW + ob * 8 + (sc << 2) + l4];
                ah[mt][2] = bw[AHIW + oa * 8 + ((1 ^ sa) << 2) + l4];
                ah[mt][3] = bw[AHIW + ob * 8 + ((1 ^ sc) << 2) + l4];
                al[mt][0] = bw[AHIW + 1024 + oa * 8 + (sa << 2) + l4];
                al[mt][1] = bw[AHIW + 1024 + ob * 8 + (sc << 2) + l4];
                al[mt][2] = bw[AHIW + 1024 + oa * 8 + ((1 ^ sa) << 2) + l4];
                al[mt][3] = bw[AHIW + 1024 + ob * 8 + ((1 ^ sc) << 2) + l4];
            }

            // ---- B fragments + MMAs in two nt-halves (keeps live regs down)
#pragma unroll
            for (int sub = 0; sub < 2; ++sub) {
                uint32_t bh[4][2], bl[4][2];
#pragma unroll
                for (int nt4 = 0; nt4 < 4; ++nt4) {
                    const int n = wk * 64 + (sub * 4 + nt4) * 8 + lr;
                    const int sn = (n >> 2) & 1;
                    bh[nt4][0] = bw[BHIW + n * 8 + (sn << 2) + l4];
                    bh[nt4][1] = bw[BHIW + n * 8 + ((1 ^ sn) << 2) + l4];
                    bl[nt4][0] = bw[BHIW + 1024 + n * 8 + (sn << 2) + l4];
                    bl[nt4][1] = bw[BHIW + 1024 + n * 8 + ((1 ^ sn) << 2) + l4];
                }
#pragma unroll
                for (int mt = 0; mt < 2; ++mt)
#pragma unroll
                    for (int nt4 = 0; nt4 < 4; ++nt4) {
                        float* acc = c[mt][sub * 4 + nt4];
                        MMA(acc, ah[mt], bh[nt4]);   // hi*hi
                        MMA(acc, al[mt], bh[nt4]);   // lo*hi
                        MMA(acc, ah[mt], bl[nt4]);   // hi*lo
                    }
            }
        }

        // ---- running argmin over this k-tile (k strictly ascending per thread)
#pragma unroll
        for (int nt = 0; nt < 8; ++nt)
#pragma unroll
            for (int q = 0; q < 2; ++q) {
                const int k = kt * KT + wk * 64 + nt * 8 + 2 * l4 + q;
                const float e2v = __ldg(&g_e2[k]);
#pragma unroll
                for (int mt = 0; mt < 2; ++mt) {
                    float v0 = fmaf(-2.f, c[mt][nt][q], e2v);       // row lr
                    if (v0 < bestv[mt * 2])     { bestv[mt * 2] = v0;     bestk[mt * 2] = k; }
                    float v1 = fmaf(-2.f, c[mt][nt][2 + q], e2v);   // row lr+8
                    if (v1 < bestv[mt * 2 + 1]) { bestv[mt * 2 + 1] = v1; bestk[mt * 2 + 1] = k; }
                }
            }
    }

    // ---- reduce across the 4 lanes of each quad (same o rows, different k)
#pragma unroll
    for (int i = 0; i < 4; ++i) {
        float v = bestv[i];
        int   k = bestk[i];
#pragma unroll
        for (int off = 1; off <= 2; off <<= 1) {
            float ov = __shfl_xor_sync(0xFFFFFFFFu, v, off);
            int   ok = __shfl_xor_sync(0xFFFFFFFFu, k, off);
            if (ov < v || (ov == v && ok < k)) { v = ov; k = ok; }
        }
        if (l4 == 0) {
            const int o = wo * 32 + (i >> 1) * 16 + (i & 1) * 8 + lr;
            smf[REDVW + wk * OT + o] = v;
            reinterpret_cast<int*>(smw)[REDKW + wk * OT + o] = k;
        }
    }
    __syncthreads();

    // ---- combine 2 k-warps (wk ascending = k ascending: strict < keeps first)
    int* ksarr = reinterpret_cast<int*>(smw) + KSOW;
    if (tid < OT) {
        float v = smf[REDVW + tid];
        int   k = reinterpret_cast<int*>(smw)[REDKW + tid];
        float ov = smf[REDVW + OT + tid];
        int   ok = reinterpret_cast<int*>(smw)[REDKW + OT + tid];
        if (ov < v) { v = ov; k = ok; }
        ksarr[tid] = k;
        if (argout) argout[b * OO + o0 + tid] = (float)k;
    }
    __syncthreads();

    // ---- gather quant[b,d,o] = emb[d, ks[o]]
    if (quant) {
        float* qb = quant + (size_t)b * DD * OO + o0;
        for (int idx = tid; idx < DD * OT; idx += NT) {
            int d = idx >> 7;
            int o = idx & (OT - 1);
            qb[d * OO + o] = emb[d * KK + ksarr[o]];
        }
    }
}

// ---------------------------------------------------------------------------
extern "C" void kernel_launch(void* const* d_in, const int* in_sizes, int n_in,
                              void* d_out, int out_size) {
    const float* x   = (const float*)d_in[0];
    const float* emb = (const float*)d_in[1];
    float* out = (float*)d_out;

    const int QN = BB * DD * OO;
    const int AN = BB * OO;

    float* quant  = nullptr;
    float* argout = nullptr;
    if (out_size >= QN) {
        quant = out;
        if (out_size >= QN + AN) argout = out + QN;
    } else if (out_size >= AN) {
        argout = out;
    }

    cudaFuncSetAttribute(vq_tc, cudaFuncAttributeMaxDynamicSharedMemorySize, SM_BYTES);

    e2_kernel<<<KK / 32, 256>>>(emb);
    splitT_emb<<<dim3(KK / 32, DD / 32), 256>>>(emb);
    splitT_x<<<dim3(OO / 32, DD / 32, BB), 256>>>(x);

    dim3 grid(OO / OT, BB);
    vq_tc<<<grid, NT, SM_BYTES>>>(emb, quant, argout);
}

// round 13
// speedup vs baseline: 1.5176x; 1.0013x over previous
#include <cuda_runtime.h>
#include <cuda_fp16.h>
#include <math_constants.h>
#include <cstdint>

#define BB 64
#define DD 256
#define OO 1024
#define KK 1024

#define OT  128              // o-tile per CTA
#define KT  128              // k-tile per outer iteration
#define NKT (KK / KT)        // 8
#define DC  32               // d per staged chunk (two m16n8k16 K steps)
#define NDC (DD / DC)        // 8
#define NG  (NKT * NDC)      // 64 pipeline iterations
#define NT  256              // 8 warps: 4 (o) x 2 (k); warp tile 32o x 64k
#define NBUF 3

// smem layout in 32-bit words. Each buffer = two 4096-word half-chunks,
// each half: Ahi 1024 | Alo 1024 | Bhi 1024 | Blo 1024 (16 d-columns).
#define HBUFW 4096
#define BUFW  (2 * HBUFW)    // 8192
#define AHIW  0
#define BHIW  2048
#define REDVW (NBUF * BUFW)  // 24576: [2][128] float
#define REDKW (REDVW + 256)
#define KSOW  (REDKW + 256)
#define SM_WORDS (KSOW + 128) // 25216
#define SM_BYTES (SM_WORDS * 4)   // 100864 -> 2 CTAs/SM

// Prep scratch: ||e||^2 + fp16 hi/lo SPLIT+TRANSPOSED copies.
__device__ float  g_e2[KK];
__device__ __half g_ehT[KK * DD];                // [k][d]
__device__ __half g_elT[KK * DD];
__device__ __half g_xhT[(size_t)BB * OO * DD];   // [b][o][d]
__device__ __half g_xlT[(size_t)BB * OO * DD];

// m16n8k16 fp16 MMA, fp32 accumulate (sm_80+ -> compiles on plain sm_100).
#define MMA(c, a, b)                                                          \
    asm volatile(                                                             \
        "mma.sync.aligned.m16n8k16.row.col.f32.f16.f16.f32 "                  \
        "{%0,%1,%2,%3}, {%4,%5,%6,%7}, {%8,%9}, {%0,%1,%2,%3};"               \
        : "+f"((c)[0]), "+f"((c)[1]), "+f"((c)[2]), "+f"((c)[3])              \
        : "r"((a)[0]), "r"((a)[1]), "r"((a)[2]), "r"((a)[3]),                 \
          "r"((b)[0]), "r"((b)[1]))

#define CP16(s, g)                                                            \
    asm volatile("cp.async.cg.shared.global [%0], [%1], 16;"                  \
        :: "r"(s), "l"((unsigned long long)__cvta_generic_to_global((const void*)(g))))
#define CP_COMMIT() asm volatile("cp.async.commit_group;" ::: "memory")
#define CP_WAIT1()  asm volatile("cp.async.wait_group 1;" ::: "memory")
#define CP_WAIT0()  asm volatile("cp.async.wait_group 0;" ::: "memory")

__device__ __forceinline__ uint32_t smem_u32(const void* p) {
    uint32_t a;
    asm("{ .reg .u64 t; cvta.to.shared.u64 t, %1; cvt.u32.u64 %0, t; }" : "=r"(a) : "l"(p));
    return a;
}

__device__ __forceinline__ void h_split(float v, __half& h, __half& l) {
    h = __float2half_rn(v);
    l = __float2half_rn(v - __half2float(h));
}

// ---------------------------------------------------------------------------
// Prep kernels (unchanged from the validated R10/R11 versions)
// ---------------------------------------------------------------------------
__global__ void e2_kernel(const float* __restrict__ emb) {   // grid 32 x 256
    __shared__ float red[8][32];
    const int k  = blockIdx.x * 32 + (threadIdx.x & 31);
    const int dg = threadIdx.x >> 5;
    float s = 0.f;
#pragma unroll
    for (int d = dg * 32; d < dg * 32 + 32; ++d) {
        float v = emb[d * KK + k];
        s = fmaf(v, v, s);
    }
    red[dg][threadIdx.x & 31] = s;
    __syncthreads();
    if (dg == 0) {
        float t = 0.f;
#pragma unroll
        for (int i = 0; i < 8; ++i) t += red[i][threadIdx.x & 31];
        g_e2[k] = t;
    }
}

__global__ void splitT_emb(const float* __restrict__ emb) {
    __shared__ float tile[32][33];
    const int tx = threadIdx.x & 31, ty = threadIdx.x >> 5;
    const int k0t = blockIdx.x * 32, d0t = blockIdx.y * 32;
#pragma unroll
    for (int i = 0; i < 4; ++i) {
        int d = ty + i * 8;
        tile[d][tx] = emb[(d0t + d) * KK + k0t + tx];
    }
    __syncthreads();
#pragma unroll
    for (int i = 0; i < 4; ++i) {
        int k = ty + i * 8;
        float v = tile[tx][k];
        __half h, l; h_split(v, h, l);
        g_ehT[(size_t)(k0t + k) * DD + d0t + tx] = h;
        g_elT[(size_t)(k0t + k) * DD + d0t + tx] = l;
    }
}

__global__ void splitT_x(const float* __restrict__ x) {
    __shared__ float tile[32][33];
    const int tx = threadIdx.x & 31, ty = threadIdx.x >> 5;
    const int o0t = blockIdx.x * 32, d0t = blockIdx.y * 32;
    const int b = blockIdx.z;
    const float* src = x + ((size_t)b * DD + d0t) * OO + o0t;
#pragma unroll
    for (int i = 0; i < 4; ++i) {
        int d = ty + i * 8;
        tile[d][tx] = src[d * OO + tx];
    }
    __syncthreads();
    __half* dh = g_xhT + ((size_t)b * OO + o0t) * DD + d0t;
    __half* dl = g_xlT + ((size_t)b * OO + o0t) * DD + d0t;
#pragma unroll
    for (int i = 0; i < 4; ++i) {
        int o = ty + i * 8;
        float v = tile[tx][o];
        __half h, l; h_split(v, h, l);
        dh[(size_t)o * DD + tx] = h;
        dl[(size_t)o * DD + tx] = l;
    }
}

// ---------------------------------------------------------------------------
// Fused 3xFP16-split mma.sync GEMM + running argmin + gather.
// CTA: one b x 128 o. Warp grid 4(o) x 2(k), warp tile 32o x 64k.
// DC=32 chunks -> 64 pipeline iterations (one __syncthreads each);
// 3-buffer cp.async pipeline with prefetch distance 2.
// ---------------------------------------------------------------------------
extern __shared__ uint32_t smw[];

__global__ __launch_bounds__(NT, 2)
void vq_tc(const float* __restrict__ emb,
           float* __restrict__ quant, float* __restrict__ argout) {
    const int tid  = threadIdx.x;
    const int lane = tid & 31;
    const int wid  = tid >> 5;
    const int wo   = wid >> 1;      // o quarter (0..3)
    const int wk   = wid & 1;       // k half (0..1)
    const int b    = blockIdx.y;
    const int o0   = blockIdx.x * OT;
    const int l4   = lane & 3;
    const int lr   = lane >> 2;

    const uint32_t sb = smem_u32(smw);
    float* smf = reinterpret_cast<float*>(smw);

    // cp.async stage for pipeline iteration g2 into buffer buf (0..2).
    // 2048 16B chunks = two DC=16 half-chunks, each in the validated layout.
    auto issue = [&](int g2, int buf) {
        const int ktn = g2 >> 3, d0 = (g2 & 7) * DC;
        const uint32_t bw = (uint32_t)buf * BUFW;
#pragma unroll
        for (int hc = 0; hc < 2; ++hc) {
            const int d0h = d0 + hc * 16;
            const uint32_t bwh = bw + hc * HBUFW;
#pragma unroll
            for (int it = 0; it < 2; ++it) {   // A: 512 chunks
                int c = tid + it * NT;
                int hl = c >> 8, o = (c >> 1) & 127, ch = c & 1;
                const __half* src = (hl ? g_xlT : g_xhT)
                    + ((size_t)b * OO + o0 + o) * DD + d0h + ch * 8;
                uint32_t dst = sb + (bwh + AHIW + hl * 1024 + o * 8
                                     + ((ch ^ ((o >> 2) & 1)) << 2)) * 4;
                CP16(dst, src);
            }
#pragma unroll
            for (int it = 0; it < 2; ++it) {   // B: 512 chunks
                int c = tid + it * NT;
                int hl = c >> 8, k = (c >> 1) & 127, ch = c & 1;
                const __half* src = (hl ? g_elT : g_ehT)
                    + (size_t)(ktn * KT + k) * DD + d0h + ch * 8;
                uint32_t dst = sb + (bwh + BHIW + hl * 1024 + k * 8
                                     + ((ch ^ ((k >> 2) & 1)) << 2)) * 4;
                CP16(dst, src);
            }
        }
    };

    issue(0, 0); CP_COMMIT();
    issue(1, 1); CP_COMMIT();

    float bestv[4] = {CUDART_INF_F, CUDART_INF_F, CUDART_INF_F, CUDART_INF_F};
    int   bestk[4] = {0, 0, 0, 0};

    int buf_c = 0, buf_i = 2;   // compute buffer, next issue buffer

    for (int kt = 0; kt < NKT; ++kt) {
        float c[2][8][4];
#pragma unroll
        for (int mt = 0; mt < 2; ++mt)
#pragma unroll
            for (int nt = 0; nt < 8; ++nt)
#pragma unroll
                for (int q = 0; q < 4; ++q) c[mt][nt][q] = 0.f;

        for (int dc = 0; dc < NDC; ++dc) {
            const int g = kt * NDC + dc;
            if (g + 2 < NG) CP_WAIT1(); else CP_WAIT0();
            __syncthreads();                 // buf g visible; MMA(g-1) done by all
            if (g + 2 < NG) {
                issue(g + 2, buf_i); CP_COMMIT();
                if (++buf_i == NBUF) buf_i = 0;
            }

#pragma unroll
            for (int hc = 0; hc < 2; ++hc) {
                const uint32_t* bw = smw + buf_c * BUFW + hc * HBUFW;

                // ---- A fragments (rows o, cols d): swizzled chunk addressing
                uint32_t ah[2][4], al[2][4];
#pragma unroll
                for (int mt = 0; mt < 2; ++mt) {
                    const int oa = wo * 32 + mt * 16 + lr;
                    const int ob = oa + 8;
                    const int sa = (oa >> 2) & 1, sc = (ob >> 2) & 1;
                    ah[mt][0] = bw[AHIW + oa * 8 + (sa << 2) + l4];
                    ah[mt][1] = bw[AHIW + ob * 8 + (sc << 2) + l4];
                    ah[mt][2] = bw[AHIW + oa * 8 + ((1 ^ sa) << 2) + l4];
                    ah[mt][3] = bw[AHIW + ob * 8 + ((1 ^ sc) << 2) + l4];
                    al[mt][0] = bw[AHIW + 1024 + oa * 8 + (sa << 2) + l4];
                    al[mt][1] = bw[AHIW + 1024 + ob * 8 + (sc << 2) + l4];
                    al[mt][2] = bw[AHIW + 1024 + oa * 8 + ((1 ^ sa) << 2) + l4];
                    al[mt][3] = bw[AHIW + 1024 + ob * 8 + ((1 ^ sc) << 2) + l4];
                }

                // ---- B fragments + MMAs in two nt-halves (limits live regs)
#pragma unroll
                for (int sub = 0; sub < 2; ++sub) {
                    uint32_t bh[4][2], bl[4][2];
#pragma unroll
                    for (int nt4 = 0; nt4 < 4; ++nt4) {
                        const int n = wk * 64 + (sub * 4 + nt4) * 8 + lr;
                        const int sn = (n >> 2) & 1;
                        bh[nt4][0] = bw[BHIW + n * 8 + (sn << 2) + l4];
                        bh[nt4][1] = bw[BHIW + n * 8 + ((1 ^ sn) << 2) + l4];
                        bl[nt4][0] = bw[BHIW + 1024 + n * 8 + (sn << 2) + l4];
                        bl[nt4][1] = bw[BHIW + 1024 + n * 8 + ((1 ^ sn) << 2) + l4];
                    }
#pragma unroll
                    for (int mt = 0; mt < 2; ++mt)
#pragma unroll
                        for (int nt4 = 0; nt4 < 4; ++nt4) {
                            float* acc = c[mt][sub * 4 + nt4];
                            MMA(acc, ah[mt], bh[nt4]);   // hi*hi
                            MMA(acc, al[mt], bh[nt4]);   // lo*hi
                            MMA(acc, ah[mt], bl[nt4]);   // hi*lo
                        }
                }
            }
            if (++buf_c == NBUF) buf_c = 0;
        }

        // ---- running argmin over this k-tile (k strictly ascending per thread)
#pragma unroll
        for (int nt = 0; nt < 8; ++nt)
#pragma unroll
            for (int q = 0; q < 2; ++q) {
                const int k = kt * KT + wk * 64 + nt * 8 + 2 * l4 + q;
                const float e2v = __ldg(&g_e2[k]);
#pragma unroll
                for (int mt = 0; mt < 2; ++mt) {
                    float v0 = fmaf(-2.f, c[mt][nt][q], e2v);       // row lr
                    if (v0 < bestv[mt * 2])     { bestv[mt * 2] = v0;     bestk[mt * 2] = k; }
                    float v1 = fmaf(-2.f, c[mt][nt][2 + q], e2v);   // row lr+8
                    if (v1 < bestv[mt * 2 + 1]) { bestv[mt * 2 + 1] = v1; bestk[mt * 2 + 1] = k; }
                }
            }
    }

    // ---- reduce across the 4 lanes of each quad (same o rows, different k)
#pragma unroll
    for (int i = 0; i < 4; ++i) {
        float v = bestv[i];
        int   k = bestk[i];
#pragma unroll
        for (int off = 1; off <= 2; off <<= 1) {
            float ov = __shfl_xor_sync(0xFFFFFFFFu, v, off);
            int   ok = __shfl_xor_sync(0xFFFFFFFFu, k, off);
            if (ov < v || (ov == v && ok < k)) { v = ov; k = ok; }
        }
        if (l4 == 0) {
            const int o = wo * 32 + (i >> 1) * 16 + (i & 1) * 8 + lr;
            smf[REDVW + wk * OT + o] = v;
            reinterpret_cast<int*>(smw)[REDKW + wk * OT + o] = k;
        }
    }
    __syncthreads();

    // ---- combine 2 k-warps (wk ascending = k ascending: strict < keeps first)
    int* ksarr = reinterpret_cast<int*>(smw) + KSOW;
    if (tid < OT) {
        float v = smf[REDVW + tid];
        int   k = reinterpret_cast<int*>(smw)[REDKW + tid];
        float ov = smf[REDVW + OT + tid];
        int   ok = reinterpret_cast<int*>(smw)[REDKW + OT + tid];
        if (ov < v) { v = ov; k = ok; }
        ksarr[tid] = k;
        if (argout) argout[b * OO + o0 + tid] = (float)k;
    }
    __syncthreads();

    // ---- gather quant[b,d,o] = emb[d, ks[o]]
    if (quant) {
        float* qb = quant + (size_t)b * DD * OO + o0;
        for (int idx = tid; idx < DD * OT; idx += NT) {
            int d = idx >> 7;
            int o = idx & (OT - 1);
            qb[d * OO + o] = emb[d * KK + ksarr[o]];
        }
    }
}

// ---------------------------------------------------------------------------
extern "C" void kernel_launch(void* const* d_in, const int* in_sizes, int n_in,
                              void* d_out, int out_size) {
    const float* x   = (const float*)d_in[0];
    const float* emb = (const float*)d_in[1];
    float* out = (float*)d_out;

    const int QN = BB * DD * OO;
    const int AN = BB * OO;

    float* quant  = nullptr;
    float* argout = nullptr;
    if (out_size >= QN) {
        quant = out;
        if (out_size >= QN + AN) argout = out + QN;
    } else if (out_size >= AN) {
        argout = out;
    }

    cudaFuncSetAttribute(vq_tc, cudaFuncAttributeMaxDynamicSharedMemorySize, SM_BYTES);

    e2_kernel<<<KK / 32, 256>>>(emb);
    splitT_emb<<<dim3(KK / 32, DD / 32), 256>>>(emb);
    splitT_x<<<dim3(OO / 32, DD / 32, BB), 256>>>(x);

    dim3 grid(OO / OT, BB);
    vq_tc<<<grid, NT, SM_BYTES>>>(emb, quant, argout);
}

// round 14
// speedup vs baseline: 1.6267x; 1.0719x over previous
#include <cuda_runtime.h>
#include <cuda_fp16.h>
#include <math_constants.h>
#include <cstdint>

#define BB 64
#define DD 256
#define OO 1024
#define KK 1024

#define OT  128              // o-tile per CTA
#define KT  128              // k-tile per outer iteration
#define NKT (KK / KT)        // 8
#define DC  32               // d per staged chunk (two m16n8k16 K steps)
#define NDC (DD / DC)        // 8
#define NG  (NKT * NDC)      // 64 pipeline iterations
#define NT  256              // 8 warps: 4 (o) x 2 (k); warp tile 32o x 64k
#define NBUF 3

// smem layout in 32-bit words. Each buffer = two 4096-word half-chunks,
// each half: Ahi 1024 | Alo 1024 | Bhi 1024 | Blo 1024 (16 d-columns).
#define HBUFW 4096
#define BUFW  (2 * HBUFW)    // 8192
#define AHIW  0
#define BHIW  2048
#define REDVW (NBUF * BUFW)  // 24576: [2][128] float
#define REDKW (REDVW + 256)
#define KSOW  (REDKW + 256)
#define SM_WORDS (KSOW + 128) // 25216
#define SM_BYTES (SM_WORDS * 4)   // 100864 -> 2 CTAs/SM

// Prep scratch: ||e||^2 + fp16 hi/lo SPLIT+TRANSPOSED copies.
__device__ float  g_e2[KK];
__device__ __half g_ehT[KK * DD];                // [k][d]
__device__ __half g_elT[KK * DD];
__device__ __half g_xhT[(size_t)BB * OO * DD];   // [b][o][d]
__device__ __half g_xlT[(size_t)BB * OO * DD];

// m16n8k16 fp16 MMA, fp32 accumulate (sm_80+ -> compiles on plain sm_100).
#define MMA(c, a, b)                                                          \
    asm volatile(                                                             \
        "mma.sync.aligned.m16n8k16.row.col.f32.f16.f16.f32 "                  \
        "{%0,%1,%2,%3}, {%4,%5,%6,%7}, {%8,%9}, {%0,%1,%2,%3};"               \
        : "+f"((c)[0]), "+f"((c)[1]), "+f"((c)[2]), "+f"((c)[3])              \
        : "r"((a)[0]), "r"((a)[1]), "r"((a)[2]), "r"((a)[3]),                 \
          "r"((b)[0]), "r"((b)[1]))

// ldmatrix x4: 4 8x8 f16 tiles, one 16B row-chunk per lane (sm_75+).
#define LDSM4(r, addr)                                                        \
    asm volatile(                                                             \
        "ldmatrix.sync.aligned.m8n8.x4.shared.b16 {%0,%1,%2,%3}, [%4];"       \
        : "=r"((r)[0]), "=r"((r)[1]), "=r"((r)[2]), "=r"((r)[3])              \
        : "r"(addr))

#define CP16(s, g)                                                            \
    asm volatile("cp.async.cg.shared.global [%0], [%1], 16;"                  \
        :: "r"(s), "l"((unsigned long long)__cvta_generic_to_global((const void*)(g))))
#define CP_COMMIT() asm volatile("cp.async.commit_group;" ::: "memory")
#define CP_WAIT1()  asm volatile("cp.async.wait_group 1;" ::: "memory")
#define CP_WAIT0()  asm volatile("cp.async.wait_group 0;" ::: "memory")

__device__ __forceinline__ uint32_t smem_u32(const void* p) {
    uint32_t a;
    asm("{ .reg .u64 t; cvta.to.shared.u64 t, %1; cvt.u32.u64 %0, t; }" : "=r"(a) : "l"(p));
    return a;
}

__device__ __forceinline__ void h_split(float v, __half& h, __half& l) {
    h = __float2half_rn(v);
    l = __float2half_rn(v - __half2float(h));
}

// ---------------------------------------------------------------------------
// Prep kernels (unchanged, validated)
// ---------------------------------------------------------------------------
__global__ void e2_kernel(const float* __restrict__ emb) {   // grid 32 x 256
    __shared__ float red[8][32];
    const int k  = blockIdx.x * 32 + (threadIdx.x & 31);
    const int dg = threadIdx.x >> 5;
    float s = 0.f;
#pragma unroll
    for (int d = dg * 32; d < dg * 32 + 32; ++d) {
        float v = emb[d * KK + k];
        s = fmaf(v, v, s);
    }
    red[dg][threadIdx.x & 31] = s;
    __syncthreads();
    if (dg == 0) {
        float t = 0.f;
#pragma unroll
        for (int i = 0; i < 8; ++i) t += red[i][threadIdx.x & 31];
        g_e2[k] = t;
    }
}

__global__ void splitT_emb(const float* __restrict__ emb) {
    __shared__ float tile[32][33];
    const int tx = threadIdx.x & 31, ty = threadIdx.x >> 5;
    const int k0t = blockIdx.x * 32, d0t = blockIdx.y * 32;
#pragma unroll
    for (int i = 0; i < 4; ++i) {
        int d = ty + i * 8;
        tile[d][tx] = emb[(d0t + d) * KK + k0t + tx];
    }
    __syncthreads();
#pragma unroll
    for (int i = 0; i < 4; ++i) {
        int k = ty + i * 8;
        float v = tile[tx][k];
        __half h, l; h_split(v, h, l);
        g_ehT[(size_t)(k0t + k) * DD + d0t + tx] = h;
        g_elT[(size_t)(k0t + k) * DD + d0t + tx] = l;
    }
}

__global__ void splitT_x(const float* __restrict__ x) {
    __shared__ float tile[32][33];
    const int tx = threadIdx.x & 31, ty = threadIdx.x >> 5;
    const int o0t = blockIdx.x * 32, d0t = blockIdx.y * 32;
    const int b = blockIdx.z;
    const float* src = x + ((size_t)b * DD + d0t) * OO + o0t;
#pragma unroll
    for (int i = 0; i < 4; ++i) {
        int d = ty + i * 8;
        tile[d][tx] = src[d * OO + tx];
    }
    __syncthreads();
    __half* dh = g_xhT + ((size_t)b * OO + o0t) * DD + d0t;
    __half* dl = g_xlT + ((size_t)b * OO + o0t) * DD + d0t;
#pragma unroll
    for (int i = 0; i < 4; ++i) {
        int o = ty + i * 8;
        float v = tile[tx][o];
        __half h, l; h_split(v, h, l);
        dh[(size_t)o * DD + tx] = h;
        dl[(size_t)o * DD + tx] = l;
    }
}

// ---------------------------------------------------------------------------
// Fused 3xFP16-split mma.sync GEMM + running argmin + gather.
// CTA: one b x 128 o. Warp grid 4(o) x 2(k), warp tile 32o x 64k.
// Fragments loaded via ldmatrix.x4 (4x fewer load instrs than scalar LDS);
// 3-buffer cp.async pipeline, prefetch distance 2, 1 barrier per dc iter.
// ---------------------------------------------------------------------------
extern __shared__ uint32_t smw[];

__global__ __launch_bounds__(NT, 2)
void vq_tc(const float* __restrict__ emb,
           float* __restrict__ quant, float* __restrict__ argout) {
    const int tid  = threadIdx.x;
    const int lane = tid & 31;
    const int wid  = tid >> 5;
    const int wo   = wid >> 1;      // o quarter (0..3)
    const int wk   = wid & 1;       // k half (0..1)
    const int b    = blockIdx.y;
    const int o0   = blockIdx.x * OT;
    const int l4   = lane & 3;
    const int lr   = lane >> 2;

    const uint32_t sb = smem_u32(smw);
    float* smf = reinterpret_cast<float*>(smw);

    // ---- per-lane ldmatrix byte offsets (within one half-chunk region) ----
    // A x4 (per mt): lanes 0-7 -> m0-7/chunk0, 8-15 -> m8-15/chunk0,
    //                16-23 -> m0-7/chunk1, 24-31 -> m8-15/chunk1.
    const int ar = (lane & 7) + ((lane >> 3) & 1) * 8;   // row within 16
    const int ac = lane >> 4;                            // chunk
    uint32_t a_off[2];
#pragma unroll
    for (int mt = 0; mt < 2; ++mt) {
        int o = wo * 32 + mt * 16 + ar;
        a_off[mt] = (uint32_t)(AHIW + o * 8 + ((ac ^ ((o >> 2) & 1)) << 2)) * 4;
    }
    // B x4 (per sub, jp): matrices = (nt=jp*2, c0), (jp*2, c1), (jp*2+1, c0), (jp*2+1, c1)
    const int bn = lane & 7;
    const int bc = (lane >> 3) & 1;
    const int bj = lane >> 4;
    uint32_t b_off[2][2];
#pragma unroll
    for (int sub = 0; sub < 2; ++sub)
#pragma unroll
        for (int jp = 0; jp < 2; ++jp) {
            int n = wk * 64 + (sub * 4 + jp * 2 + bj) * 8 + bn;
            b_off[sub][jp] = (uint32_t)(BHIW + n * 8 + ((bc ^ ((n >> 2) & 1)) << 2)) * 4;
        }

    // cp.async stage for pipeline iteration g2 into buffer buf (unchanged).
    auto issue = [&](int g2, int buf) {
        const int ktn = g2 >> 3, d0 = (g2 & 7) * DC;
        const uint32_t bw = (uint32_t)buf * BUFW;
#pragma unroll
        for (int hc = 0; hc < 2; ++hc) {
            const int d0h = d0 + hc * 16;
            const uint32_t bwh = bw + hc * HBUFW;
#pragma unroll
            for (int it = 0; it < 2; ++it) {   // A: 512 chunks
                int c = tid + it * NT;
                int hl = c >> 8, o = (c >> 1) & 127, ch = c & 1;
                const __half* src = (hl ? g_xlT : g_xhT)
                    + ((size_t)b * OO + o0 + o) * DD + d0h + ch * 8;
                uint32_t dst = sb + (bwh + AHIW + hl * 1024 + o * 8
                                     + ((ch ^ ((o >> 2) & 1)) << 2)) * 4;
                CP16(dst, src);
            }
#pragma unroll
            for (int it = 0; it < 2; ++it) {   // B: 512 chunks
                int c = tid + it * NT;
                int hl = c >> 8, k = (c >> 1) & 127, ch = c & 1;
                const __half* src = (hl ? g_elT : g_ehT)
                    + (size_t)(ktn * KT + k) * DD + d0h + ch * 8;
                uint32_t dst = sb + (bwh + BHIW + hl * 1024 + k * 8
                                     + ((ch ^ ((k >> 2) & 1)) << 2)) * 4;
                CP16(dst, src);
            }
        }
    };

    issue(0, 0); CP_COMMIT();
    issue(1, 1); CP_COMMIT();

    float bestv[4] = {CUDART_INF_F, CUDART_INF_F, CUDART_INF_F, CUDART_INF_F};
    int   bestk[4] = {0, 0, 0, 0};

    int buf_c = 0, buf_i = 2;   // compute buffer, next issue buffer

    for (int kt = 0; kt < NKT; ++kt) {
        float c[2][8][4];
#pragma unroll
        for (int mt = 0; mt < 2; ++mt)
#pragma unroll
            for (int nt = 0; nt < 8; ++nt)
#pragma unroll
                for (int q = 0; q < 4; ++q) c[mt][nt][q] = 0.f;

        for (int dc = 0; dc < NDC; ++dc) {
            const int g = kt * NDC + dc;
            if (g + 2 < NG) CP_WAIT1(); else CP_WAIT0();
            __syncthreads();                 // buf g visible; MMA(g-1) done by all
            if (g + 2 < NG) {
                issue(g + 2, buf_i); CP_COMMIT();
                if (++buf_i == NBUF) buf_i = 0;
            }

#pragma unroll
            for (int hc = 0; hc < 2; ++hc) {
                const uint32_t rb = sb + (uint32_t)(buf_c * BUFW + hc * HBUFW) * 4;

                // ---- A fragments: 4 ldmatrix.x4 (hi + lo, 2 mt each)
                uint32_t ah[2][4], al[2][4];
                LDSM4(ah[0], rb + a_off[0]);
                LDSM4(ah[1], rb + a_off[1]);
                LDSM4(al[0], rb + a_off[0] + 4096);   // ALO = AHIW + 1024 words
                LDSM4(al[1], rb + a_off[1] + 4096);

                // ---- B fragments + MMAs in two nt-halves
#pragma unroll
                for (int sub = 0; sub < 2; ++sub) {
                    uint32_t bh[4][2], bl[4][2];
                    LDSM4(&bh[0][0], rb + b_off[sub][0]);
                    LDSM4(&bh[2][0], rb + b_off[sub][1]);
                    LDSM4(&bl[0][0], rb + b_off[sub][0] + 4096);  // BLO
                    LDSM4(&bl[2][0], rb + b_off[sub][1] + 4096);
#pragma unroll
                    for (int mt = 0; mt < 2; ++mt)
#pragma unroll
                        for (int nt4 = 0; nt4 < 4; ++nt4) {
                            float* acc = c[mt][sub * 4 + nt4];
                            MMA(acc, ah[mt], bh[nt4]);   // hi*hi
                            MMA(acc, al[mt], bh[nt4]);   // lo*hi
                            MMA(acc, ah[mt], bl[nt4]);   // hi*lo
                        }
                }
            }
            if (++buf_c == NBUF) buf_c = 0;
        }

        // ---- running argmin over this k-tile (k strictly ascending per thread)
#pragma unroll
        for (int nt = 0; nt < 8; ++nt)
#pragma unroll
            for (int q = 0; q < 2; ++q) {
                const int k = kt * KT + wk * 64 + nt * 8 + 2 * l4 + q;
                const float e2v = __ldg(&g_e2[k]);
#pragma unroll
                for (int mt = 0; mt < 2; ++mt) {
                    float v0 = fmaf(-2.f, c[mt][nt][q], e2v);       // row lr
                    if (v0 < bestv[mt * 2])     { bestv[mt * 2] = v0;     bestk[mt * 2] = k; }
                    float v1 = fmaf(-2.f, c[mt][nt][2 + q], e2v);   // row lr+8
                    if (v1 < bestv[mt * 2 + 1]) { bestv[mt * 2 + 1] = v1; bestk[mt * 2 + 1] = k; }
                }
            }
    }

    // ---- reduce across the 4 lanes of each quad (same o rows, different k)
#pragma unroll
    for (int i = 0; i < 4; ++i) {
        float v = bestv[i];
        int   k = bestk[i];
#pragma unroll
        for (int off = 1; off <= 2; off <<= 1) {
            float ov = __shfl_xor_sync(0xFFFFFFFFu, v, off);
            int   ok = __shfl_xor_sync(0xFFFFFFFFu, k, off);
            if (ov < v || (ov == v && ok < k)) { v = ov; k = ok; }
        }
        if (l4 == 0) {
            const int o = wo * 32 + (i >> 1) * 16 + (i & 1) * 8 + lr;
            smf[REDVW + wk * OT + o] = v;
            reinterpret_cast<int*>(smw)[REDKW + wk * OT + o] = k;
        }
    }
    __syncthreads();

    // ---- combine 2 k-warps (wk ascending = k ascending: strict < keeps first)
    int* ksarr = reinterpret_cast<int*>(smw) + KSOW;
    if (tid < OT) {
        float v = smf[REDVW + tid];
        int   k = reinterpret_cast<int*>(smw)[REDKW + tid];
        float ov = smf[REDVW + OT + tid];
        int   ok = reinterpret_cast<int*>(smw)[REDKW + OT + tid];
        if (ov < v) { v = ov; k = ok; }
        ksarr[tid] = k;
        if (argout) argout[b * OO + o0 + tid] = (float)k;
    }
    __syncthreads();

    // ---- gather quant[b,d,o] = emb[d, ks[o]]
    if (quant) {
        float* qb = quant + (size_t)b * DD * OO + o0;
        for (int idx = tid; idx < DD * OT; idx += NT) {
            int d = idx >> 7;
            int o = idx & (OT - 1);
            qb[d * OO + o] = emb[d * KK + ksarr[o]];
        }
    }
}

// ---------------------------------------------------------------------------
extern "C" void kernel_launch(void* const* d_in, const int* in_sizes, int n_in,
                              void* d_out, int out_size) {
    const float* x   = (const float*)d_in[0];
    const float* emb = (const float*)d_in[1];
    float* out = (float*)d_out;

    const int QN = BB * DD * OO;
    const int AN = BB * OO;

    float* quant  = nullptr;
    float* argout = nullptr;
    if (out_size >= QN) {
        quant = out;
        if (out_size >= QN + AN) argout = out + QN;
    } else if (out_size >= AN) {
        argout = out;
    }

    cudaFuncSetAttribute(vq_tc, cudaFuncAttributeMaxDynamicSharedMemorySize, SM_BYTES);

    e2_kernel<<<KK / 32, 256>>>(emb);
    splitT_emb<<<dim3(KK / 32, DD / 32), 256>>>(emb);
    splitT_x<<<dim3(OO / 32, DD / 32, BB), 256>>>(x);

    dim3 grid(OO / OT, BB);
    vq_tc<<<grid, NT, SM_BYTES>>>(emb, quant, argout);
}

// round 15
// speedup vs baseline: 1.7687x; 1.0873x over previous
#include <cuda_runtime.h>
#include <cuda_fp16.h>
#include <math_constants.h>
#include <cstdint>

#define BB 64
#define DD 256
#define OO 1024
#define KK 1024

#define OT  64               // o-tile per CTA
#define KT  128              // k-tile per outer iteration
#define NKT (KK / KT)        // 8
#define DC  32               // d per staged chunk (two m16n8k16 K steps)
#define NDC (DD / DC)        // 8
#define NG  (NKT * NDC)      // 64 pipeline iterations
#define NT  128              // 4 warps: 2 (o) x 2 (k); warp tile 32o x 64k
#define NBUF 2

// smem layout in 32-bit words. Each buffer = two 3072-word half-chunks,
// each half: Ahi 512 | Alo 512 | Bhi 1024 | Blo 1024 (16 d-columns).
#define HBUFW 3072
#define BUFW  (2 * HBUFW)    // 6144
#define AHIW  0
#define BHIW  1024
#define REDVW (NBUF * BUFW)  // 12288: [2][64] float
#define REDKW (REDVW + 128)
#define KSOW  (REDKW + 128)
#define SM_WORDS (KSOW + 64) // 12608
#define SM_BYTES (SM_WORDS * 4)   // 50432 -> 4 CTAs/SM

// Prep scratch: ||e||^2 + fp16 hi/lo SPLIT+TRANSPOSED copies.
__device__ float  g_e2[KK];
__device__ __half g_ehT[KK * DD];                // [k][d]
__device__ __half g_elT[KK * DD];
__device__ __half g_xhT[(size_t)BB * OO * DD];   // [b][o][d]
__device__ __half g_xlT[(size_t)BB * OO * DD];

// m16n8k16 fp16 MMA, fp32 accumulate (sm_80+ -> compiles on plain sm_100).
#define MMA(c, a, b)                                                          \
    asm volatile(                                                             \
        "mma.sync.aligned.m16n8k16.row.col.f32.f16.f16.f32 "                  \
        "{%0,%1,%2,%3}, {%4,%5,%6,%7}, {%8,%9}, {%0,%1,%2,%3};"               \
        : "+f"((c)[0]), "+f"((c)[1]), "+f"((c)[2]), "+f"((c)[3])              \
        : "r"((a)[0]), "r"((a)[1]), "r"((a)[2]), "r"((a)[3]),                 \
          "r"((b)[0]), "r"((b)[1]))

// ldmatrix x4: 4 8x8 f16 tiles, one 16B row-chunk per lane (sm_75+).
#define LDSM4(r, addr)                                                        \
    asm volatile(                                                             \
        "ldmatrix.sync.aligned.m8n8.x4.shared.b16 {%0,%1,%2,%3}, [%4];"       \
        : "=r"((r)[0]), "=r"((r)[1]), "=r"((r)[2]), "=r"((r)[3])              \
        : "r"(addr))

#define CP16(s, g)                                                            \
    asm volatile("cp.async.cg.shared.global [%0], [%1], 16;"                  \
        :: "r"(s), "l"((unsigned long long)__cvta_generic_to_global((const void*)(g))))
#define CP_COMMIT() asm volatile("cp.async.commit_group;" ::: "memory")
#define CP_WAIT0()  asm volatile("cp.async.wait_group 0;" ::: "memory")

__device__ __forceinline__ uint32_t smem_u32(const void* p) {
    uint32_t a;
    asm("{ .reg .u64 t; cvta.to.shared.u64 t, %1; cvt.u32.u64 %0, t; }" : "=r"(a) : "l"(p));
    return a;
}

__device__ __forceinline__ void h_split(float v, __half& h, __half& l) {
    h = __float2half_rn(v);
    l = __float2half_rn(v - __half2float(h));
}

// ---------------------------------------------------------------------------
// Prep kernels (unchanged, validated)
// ---------------------------------------------------------------------------
__global__ void e2_kernel(const float* __restrict__ emb) {   // grid 32 x 256
    __shared__ float red[8][32];
    const int k  = blockIdx.x * 32 + (threadIdx.x & 31);
    const int dg = threadIdx.x >> 5;
    float s = 0.f;
#pragma unroll
    for (int d = dg * 32; d < dg * 32 + 32; ++d) {
        float v = emb[d * KK + k];
        s = fmaf(v, v, s);
    }
    red[dg][threadIdx.x & 31] = s;
    __syncthreads();
    if (dg == 0) {
        float t = 0.f;
#pragma unroll
        for (int i = 0; i < 8; ++i) t += red[i][threadIdx.x & 31];
        g_e2[k] = t;
    }
}

__global__ void splitT_emb(const float* __restrict__ emb) {
    __shared__ float tile[32][33];
    const int tx = threadIdx.x & 31, ty = threadIdx.x >> 5;
    const int k0t = blockIdx.x * 32, d0t = blockIdx.y * 32;
#pragma unroll
    for (int i = 0; i < 4; ++i) {
        int d = ty + i * 8;
        tile[d][tx] = emb[(d0t + d) * KK + k0t + tx];
    }
    __syncthreads();
#pragma unroll
    for (int i = 0; i < 4; ++i) {
        int k = ty + i * 8;
        float v = tile[tx][k];
        __half h, l; h_split(v, h, l);
        g_ehT[(size_t)(k0t + k) * DD + d0t + tx] = h;
        g_elT[(size_t)(k0t + k) * DD + d0t + tx] = l;
    }
}

__global__ void splitT_x(const float* __restrict__ x) {
    __shared__ float tile[32][33];
    const int tx = threadIdx.x & 31, ty = threadIdx.x >> 5;
    const int o0t = blockIdx.x * 32, d0t = blockIdx.y * 32;
    const int b = blockIdx.z;
    const float* src = x + ((size_t)b * DD + d0t) * OO + o0t;
#pragma unroll
    for (int i = 0; i < 4; ++i) {
        int d = ty + i * 8;
        tile[d][tx] = src[d * OO + tx];
    }
    __syncthreads();
    __half* dh = g_xhT + ((size_t)b * OO + o0t) * DD + d0t;
    __half* dl = g_xlT + ((size_t)b * OO + o0t) * DD + d0t;
#pragma unroll
    for (int i = 0; i < 4; ++i) {
        int o = ty + i * 8;
        float v = tile[tx][o];
        __half h, l; h_split(v, h, l);
        dh[(size_t)o * DD + tx] = h;
        dl[(size_t)o * DD + tx] = l;
    }
}

// ---------------------------------------------------------------------------
// Fused 3xFP16-split mma.sync GEMM + running argmin + gather.
// CTA: one b x 64 o, 4 warps (2o x 2k), warp tile 32o x 64k.
// 4 CTAs/SM, each its own small barrier domain -> staggered phases keep the
// tensor pipe fed. 2-buffer cp.async pipeline, ldmatrix.x4 fragment loads.
// ---------------------------------------------------------------------------
extern __shared__ uint32_t smw[];

__global__ __launch_bounds__(NT, 4)
void vq_tc(const float* __restrict__ emb,
           float* __restrict__ quant, float* __restrict__ argout) {
    const int tid  = threadIdx.x;
    const int lane = tid & 31;
    const int wid  = tid >> 5;
    const int wo   = wid >> 1;      // o half (0..1)
    const int wk   = wid & 1;       // k half (0..1)
    const int b    = blockIdx.y;
    const int o0   = blockIdx.x * OT;
    const int l4   = lane & 3;
    const int lr   = lane >> 2;

    const uint32_t sb = smem_u32(smw);
    float* smf = reinterpret_cast<float*>(smw);

    // ---- per-lane ldmatrix byte offsets (within one half-chunk region) ----
    const int ar = (lane & 7) + ((lane >> 3) & 1) * 8;   // row within 16
    const int ac = lane >> 4;                            // chunk
    uint32_t a_off[2];
#pragma unroll
    for (int mt = 0; mt < 2; ++mt) {
        int o = wo * 32 + mt * 16 + ar;
        a_off[mt] = (uint32_t)(AHIW + o * 8 + ((ac ^ ((o >> 2) & 1)) << 2)) * 4;
    }
    const int bn = lane & 7;
    const int bc = (lane >> 3) & 1;
    const int bj = lane >> 4;
    uint32_t b_off[2][2];
#pragma unroll
    for (int sub = 0; sub < 2; ++sub)
#pragma unroll
        for (int jp = 0; jp < 2; ++jp) {
            int n = wk * 64 + (sub * 4 + jp * 2 + bj) * 8 + bn;
            b_off[sub][jp] = (uint32_t)(BHIW + n * 8 + ((bc ^ ((n >> 2) & 1)) << 2)) * 4;
        }

    // cp.async stage for pipeline iteration g2 into buffer buf.
    auto issue = [&](int g2, int buf) {
        const int ktn = g2 >> 3, d0 = (g2 & 7) * DC;
        const uint32_t bw = (uint32_t)buf * BUFW;
#pragma unroll
        for (int hc = 0; hc < 2; ++hc) {
            const int d0h = d0 + hc * 16;
            const uint32_t bwh = bw + hc * HBUFW;
#pragma unroll
            for (int it = 0; it < 2; ++it) {   // A: 256 chunks (hi 128 + lo 128)
                int c = tid + it * NT;
                int hl = c >> 7, o = (c >> 1) & 63, ch = c & 1;
                const __half* src = (hl ? g_xlT : g_xhT)
                    + ((size_t)b * OO + o0 + o) * DD + d0h + ch * 8;
                uint32_t dst = sb + (bwh + AHIW + hl * 512 + o * 8
                                     + ((ch ^ ((o >> 2) & 1)) << 2)) * 4;
                CP16(dst, src);
            }
#pragma unroll
            for (int it = 0; it < 4; ++it) {   // B: 512 chunks (hi 256 + lo 256)
                int c = tid + it * NT;
                int hl = c >> 8, k = (c >> 1) & 127, ch = c & 1;
                const __half* src = (hl ? g_elT : g_ehT)
                    + (size_t)(ktn * KT + k) * DD + d0h + ch * 8;
                uint32_t dst = sb + (bwh + BHIW + hl * 1024 + k * 8
                                     + ((ch ^ ((k >> 2) & 1)) << 2)) * 4;
                CP16(dst, src);
            }
        }
    };

    issue(0, 0); CP_COMMIT();

    float bestv[4] = {CUDART_INF_F, CUDART_INF_F, CUDART_INF_F, CUDART_INF_F};
    int   bestk[4] = {0, 0, 0, 0};

    for (int kt = 0; kt < NKT; ++kt) {
        float c[2][8][4];
#pragma unroll
        for (int mt = 0; mt < 2; ++mt)
#pragma unroll
            for (int nt = 0; nt < 8; ++nt)
#pragma unroll
                for (int q = 0; q < 4; ++q) c[mt][nt][q] = 0.f;

        for (int dc = 0; dc < NDC; ++dc) {
            const int g = kt * NDC + dc;
            CP_WAIT0();                      // group g landed
            __syncthreads();                 // + prev compute done -> other buf free
            if (g + 1 < NG) { issue(g + 1, (g + 1) & 1); CP_COMMIT(); }

#pragma unroll
            for (int hc = 0; hc < 2; ++hc) {
                const uint32_t rb = sb + (uint32_t)((g & 1) * BUFW + hc * HBUFW) * 4;

                // ---- A fragments: 4 ldmatrix.x4 (hi + lo, 2 mt each)
                uint32_t ah[2][4], al[2][4];
                LDSM4(ah[0], rb + a_off[0]);
                LDSM4(ah[1], rb + a_off[1]);
                LDSM4(al[0], rb + a_off[0] + 2048);   // ALO = AHIW + 512 words
                LDSM4(al[1], rb + a_off[1] + 2048);

                // ---- B fragments + MMAs in two nt-halves
#pragma unroll
                for (int sub = 0; sub < 2; ++sub) {
                    uint32_t bh[4][2], bl[4][2];
                    LDSM4(&bh[0][0], rb + b_off[sub][0]);
                    LDSM4(&bh[2][0], rb + b_off[sub][1]);
                    LDSM4(&bl[0][0], rb + b_off[sub][0] + 4096);  // BLO = BHIW + 1024
                    LDSM4(&bl[2][0], rb + b_off[sub][1] + 4096);
#pragma unroll
                    for (int mt = 0; mt < 2; ++mt)
#pragma unroll
                        for (int nt4 = 0; nt4 < 4; ++nt4) {
                            float* acc = c[mt][sub * 4 + nt4];
                            MMA(acc, ah[mt], bh[nt4]);   // hi*hi
                            MMA(acc, al[mt], bh[nt4]);   // lo*hi
                            MMA(acc, ah[mt], bl[nt4]);   // hi*lo
                        }
                }
            }
        }

        // ---- running argmin over this k-tile (k strictly ascending per thread)
#pragma unroll
        for (int nt = 0; nt < 8; ++nt)
#pragma unroll
            for (int q = 0; q < 2; ++q) {
                const int k = kt * KT + wk * 64 + nt * 8 + 2 * l4 + q;
                const float e2v = __ldg(&g_e2[k]);
#pragma unroll
                for (int mt = 0; mt < 2; ++mt) {
                    float v0 = fmaf(-2.f, c[mt][nt][q], e2v);       // row lr
                    if (v0 < bestv[mt * 2])     { bestv[mt * 2] = v0;     bestk[mt * 2] = k; }
                    float v1 = fmaf(-2.f, c[mt][nt][2 + q], e2v);   // row lr+8
                    if (v1 < bestv[mt * 2 + 1]) { bestv[mt * 2 + 1] = v1; bestk[mt * 2 + 1] = k; }
                }
            }
    }

    // ---- reduce across the 4 lanes of each quad (same o rows, different k)
#pragma unroll
    for (int i = 0; i < 4; ++i) {
        float v = bestv[i];
        int   k = bestk[i];
#pragma unroll
        for (int off = 1; off <= 2; off <<= 1) {
            float ov = __shfl_xor_sync(0xFFFFFFFFu, v, off);
            int   ok = __shfl_xor_sync(0xFFFFFFFFu, k, off);
            if (ov < v || (ov == v && ok < k)) { v = ov; k = ok; }
        }
        if (l4 == 0) {
            const int o = wo * 32 + (i >> 1) * 16 + (i & 1) * 8 + lr;
            smf[REDVW + wk * OT + o] = v;
            reinterpret_cast<int*>(smw)[REDKW + wk * OT + o] = k;
        }
    }
    __syncthreads();

    // ---- combine 2 k-warps (wk ascending = k ascending: strict < keeps first)
    int* ksarr = reinterpret_cast<int*>(smw) + KSOW;
    if (tid < OT) {
        float v = smf[REDVW + tid];
        int   k = reinterpret_cast<int*>(smw)[REDKW + tid];
        float ov = smf[REDVW + OT + tid];
        int   ok = reinterpret_cast<int*>(smw)[REDKW + OT + tid];
        if (ov < v) { v = ov; k = ok; }
        ksarr[tid] = k;
        if (argout) argout[b * OO + o0 + tid] = (float)k;
    }
    __syncthreads();

    // ---- gather quant[b,d,o] = emb[d, ks[o]]
    if (quant) {
        float* qb = quant + (size_t)b * DD * OO + o0;
        for (int idx = tid; idx < DD * OT; idx += NT) {
            int d = idx >> 6;
            int o = idx & (OT - 1);
            qb[d * OO + o] = emb[d * KK + ksarr[o]];
        }
    }
}

// ---------------------------------------------------------------------------
extern "C" void kernel_launch(void* const* d_in, const int* in_sizes, int n_in,
                              void* d_out, int out_size) {
    const float* x   = (const float*)d_in[0];
    const float* emb = (const float*)d_in[1];
    float* out = (float*)d_out;

    const int QN = BB * DD * OO;
    const int AN = BB * OO;

    float* quant  = nullptr;
    float* argout = nullptr;
    if (out_size >= QN) {
        quant = out;
        if (out_size >= QN + AN) argout = out + QN;
    } else if (out_size >= AN) {
        argout = out;
    }

    cudaFuncSetAttribute(vq_tc, cudaFuncAttributeMaxDynamicSharedMemorySize, SM_BYTES);

    e2_kernel<<<KK / 32, 256>>>(emb);
    splitT_emb<<<dim3(KK / 32, DD / 32), 256>>>(emb);
    splitT_x<<<dim3(OO / 32, DD / 32, BB), 256>>>(x);

    dim3 grid(OO / OT, BB);
    vq_tc<<<grid, NT, SM_BYTES>>>(emb, quant, argout);
}

// round 17
// speedup vs baseline: 1.9175x; 1.0841x over previous
#include <cuda_runtime.h>
#include <cuda_fp16.h>
#include <math_constants.h>
#include <cstdint>

#define BB 64
#define DD 256
#define OO 1024
#define KK 1024

#define OT  64               // o-tile per CTA
#define KT  128              // k-tile per outer iteration
#define NKT (KK / KT)        // 8
#define DC  16               // d per staged chunk (one m16n8k16 K step)
#define NDC (DD / DC)        // 16
#define NG  (NKT * NDC)      // 128 pipeline iterations
#define NT  128              // 4 warps: 2 (o) x 2 (k); warp tile 32o x 64k
#define NBUF 3

// smem layout in 32-bit words. One buffer = one DC=16 chunk:
// Ahi 512 | Alo 512 | Bhi 1024 | Blo 1024.
#define BUFW  3072
#define AHIW  0
#define BHIW  1024
#define REDVW (NBUF * BUFW)  // 9216: [2][64] float
#define REDKW (REDVW + 128)
#define KSOW  (REDKW + 128)
#define SM_WORDS (KSOW + 64) // 9536
#define SM_BYTES (SM_WORDS * 4)   // 38144 -> 4 CTAs/SM

// Prep scratch: ||e||^2 + fp16 hi/lo SPLIT+TRANSPOSED copies.
__device__ float  g_e2[KK];
__device__ __half g_ehT[KK * DD];                // [k][d]
__device__ __half g_elT[KK * DD];
__device__ __half g_xhT[(size_t)BB * OO * DD];   // [b][o][d]
__device__ __half g_xlT[(size_t)BB * OO * DD];

// m16n8k16 fp16 MMA, fp32 accumulate (sm_80+ -> compiles on plain sm_100).
#define MMA(c, a, b)                                                          \
    asm volatile(                                                             \
        "mma.sync.aligned.m16n8k16.row.col.f32.f16.f16.f32 "                  \
        "{%0,%1,%2,%3}, {%4,%5,%6,%7}, {%8,%9}, {%0,%1,%2,%3};"               \
        : "+f"((c)[0]), "+f"((c)[1]), "+f"((c)[2]), "+f"((c)[3])              \
        : "r"((a)[0]), "r"((a)[1]), "r"((a)[2]), "r"((a)[3]),                 \
          "r"((b)[0]), "r"((b)[1]))

// ldmatrix x4: 4 8x8 f16 tiles, one 16B row-chunk per lane (sm_75+).
#define LDSM4(r, addr)                                                        \
    asm volatile(                                                             \
        "ldmatrix.sync.aligned.m8n8.x4.shared.b16 {%0,%1,%2,%3}, [%4];"       \
        : "=r"((r)[0]), "=r"((r)[1]), "=r"((r)[2]), "=r"((r)[3])              \
        : "r"(addr))

#define CP16(s, g)                                                            \
    asm volatile("cp.async.cg.shared.global [%0], [%1], 16;"                  \
        :: "r"(s), "l"((unsigned long long)__cvta_generic_to_global((const void*)(g))))
#define CP_COMMIT() asm volatile("cp.async.commit_group;" ::: "memory")
#define CP_WAIT1()  asm volatile("cp.async.wait_group 1;" ::: "memory")
#define CP_WAIT0()  asm volatile("cp.async.wait_group 0;" ::: "memory")

__device__ __forceinline__ uint32_t smem_u32(const void* p) {
    uint32_t a;
    asm("{ .reg .u64 t; cvta.to.shared.u64 t, %1; cvt.u32.u64 %0, t; }" : "=r"(a) : "l"(p));
    return a;
}

__device__ __forceinline__ void h_split(float v, __half& h, __half& l) {
    h = __float2half_rn(v);
    l = __float2half_rn(v - __half2float(h));
}

// ---------------------------------------------------------------------------
// Prep kernels (unchanged, validated)
// ---------------------------------------------------------------------------
__global__ void e2_kernel(const float* __restrict__ emb) {   // grid 32 x 256
    __shared__ float red[8][32];
    const int k  = blockIdx.x * 32 + (threadIdx.x & 31);
    const int dg = threadIdx.x >> 5;
    float s = 0.f;
#pragma unroll
    for (int d = dg * 32; d < dg * 32 + 32; ++d) {
        float v = emb[d * KK + k];
        s = fmaf(v, v, s);
    }
    red[dg][threadIdx.x & 31] = s;
    __syncthreads();
    if (dg == 0) {
        float t = 0.f;
#pragma unroll
        for (int i = 0; i < 8; ++i) t += red[i][threadIdx.x & 31];
        g_e2[k] = t;
    }
}

__global__ void splitT_emb(const float* __restrict__ emb) {
    __shared__ float tile[32][33];
    const int tx = threadIdx.x & 31, ty = threadIdx.x >> 5;
    const int k0t = blockIdx.x * 32, d0t = blockIdx.y * 32;
#pragma unroll
    for (int i = 0; i < 4; ++i) {
        int d = ty + i * 8;
        tile[d][tx] = emb[(d0t + d) * KK + k0t + tx];
    }
    __syncthreads();
#pragma unroll
    for (int i = 0; i < 4; ++i) {
        int k = ty + i * 8;
        float v = tile[tx][k];
        __half h, l; h_split(v, h, l);
        g_ehT[(size_t)(k0t + k) * DD + d0t + tx] = h;
        g_elT[(size_t)(k0t + k) * DD + d0t + tx] = l;
    }
}

__global__ void splitT_x(const float* __restrict__ x) {
    __shared__ float tile[32][33];
    const int tx = threadIdx.x & 31, ty = threadIdx.x >> 5;
    const int o0t = blockIdx.x * 32, d0t = blockIdx.y * 32;
    const int b = blockIdx.z;
    const float* src = x + ((size_t)b * DD + d0t) * OO + o0t;
#pragma unroll
    for (int i = 0; i < 4; ++i) {
        int d = ty + i * 8;
        tile[d][tx] = src[d * OO + tx];
    }
    __syncthreads();
    __half* dh = g_xhT + ((size_t)b * OO + o0t) * DD + d0t;
    __half* dl = g_xlT + ((size_t)b * OO + o0t) * DD + d0t;
#pragma unroll
    for (int i = 0; i < 4; ++i) {
        int o = ty + i * 8;
        float v = tile[tx][o];
        __half h, l; h_split(v, h, l);
        dh[(size_t)o * DD + tx] = h;
        dl[(size_t)o * DD + tx] = l;
    }
}

// ---------------------------------------------------------------------------
// Fused 3xFP16-split mma.sync GEMM + running argmin + gather.
// CTA: one b x 64 o, 4 warps (2o x 2k), warp tile 32o x 64k.
// 4 CTAs/SM (staggered barrier domains) AND a 3-buffer cp.async pipeline
// with prefetch distance 2. ldmatrix.x4 fragment loads, XOR-chunk swizzle.
// ---------------------------------------------------------------------------
extern __shared__ uint32_t smw[];

__global__ __launch_bounds__(NT, 4)
void vq_tc(const float* __restrict__ emb,
           float* __restrict__ quant, float* __restrict__ argout) {
    const int tid  = threadIdx.x;
    const int lane = tid & 31;
    const int wid  = tid >> 5;
    const int wo   = wid >> 1;      // o half (0..1)
    const int wk   = wid & 1;       // k half (0..1)
    const int b    = blockIdx.y;
    const int o0   = blockIdx.x * OT;
    const int l4   = lane & 3;
    const int lr   = lane >> 2;

    const uint32_t sb = smem_u32(smw);
    float* smf = reinterpret_cast<float*>(smw);

    // ---- per-lane ldmatrix byte offsets (within one buffer) ----
    const int ar = (lane & 7) + ((lane >> 3) & 1) * 8;   // row within 16
    const int ac = lane >> 4;                            // chunk
    uint32_t a_off[2];
#pragma unroll
    for (int mt = 0; mt < 2; ++mt) {
        int o = wo * 32 + mt * 16 + ar;
        a_off[mt] = (uint32_t)(AHIW + o * 8 + ((ac ^ ((o >> 2) & 1)) << 2)) * 4;
    }
    const int bn = lane & 7;
    const int bc = (lane >> 3) & 1;
    const int bj = lane >> 4;
    uint32_t b_off[2][2];
#pragma unroll
    for (int sub = 0; sub < 2; ++sub)
#pragma unroll
        for (int jp = 0; jp < 2; ++jp) {
            int n = wk * 64 + (sub * 4 + jp * 2 + bj) * 8 + bn;
            b_off[sub][jp] = (uint32_t)(BHIW + n * 8 + ((bc ^ ((n >> 2) & 1)) << 2)) * 4;
        }

    // cp.async stage for pipeline iteration g2 into buffer buf (0..2).
    auto issue = [&](int g2, int buf) {
        const int ktn = g2 >> 4, d0 = (g2 & 15) * DC;
        const uint32_t bw = (uint32_t)buf * BUFW;
#pragma unroll
        for (int it = 0; it < 2; ++it) {   // A: 256 chunks (hi 128 + lo 128)
            int c = tid + it * NT;
            int hl = c >> 7, o = (c >> 1) & 63, ch = c & 1;
            const __half* src = (hl ? g_xlT : g_xhT)
                + ((size_t)b * OO + o0 + o) * DD + d0 + ch * 8;
            uint32_t dst = sb + (bw + AHIW + hl * 512 + o * 8
                                 + ((ch ^ ((o >> 2) & 1)) << 2)) * 4;
            CP16(dst, src);
        }
#pragma unroll
        for (int it = 0; it < 4; ++it) {   // B: 512 chunks (hi 256 + lo 256)
            int c = tid + it * NT;
            int hl = c >> 8, k = (c >> 1) & 127, ch = c & 1;
            const __half* src = (hl ? g_elT : g_ehT)
                + (size_t)(ktn * KT + k) * DD + d0 + ch * 8;
            uint32_t dst = sb + (bw + BHIW + hl * 1024 + k * 8
                                 + ((ch ^ ((k >> 2) & 1)) << 2)) * 4;
            CP16(dst, src);
        }
    };

    issue(0, 0); CP_COMMIT();
    issue(1, 1); CP_COMMIT();

    float bestv[4] = {CUDART_INF_F, CUDART_INF_F, CUDART_INF_F, CUDART_INF_F};
    int   bestk[4] = {0, 0, 0, 0};

    int buf_c = 0, buf_i = 2;   // compute buffer, next issue buffer

    for (int kt = 0; kt < NKT; ++kt) {
        float c[2][8][4];
#pragma unroll
        for (int mt = 0; mt < 2; ++mt)
#pragma unroll
            for (int nt = 0; nt < 8; ++nt)
#pragma unroll
                for (int q = 0; q < 4; ++q) c[mt][nt][q] = 0.f;

        for (int dc = 0; dc < NDC; ++dc) {
            const int g = kt * NDC + dc;
            if (g + 1 < NG) CP_WAIT1(); else CP_WAIT0();   // group g landed
            __syncthreads();                 // + compute(g-1) done -> its buf free
            if (g + 2 < NG) {
                issue(g + 2, buf_i); CP_COMMIT();
                if (++buf_i == NBUF) buf_i = 0;
            }

            const uint32_t rb = sb + (uint32_t)(buf_c * BUFW) * 4;

            // ---- A fragments: 4 ldmatrix.x4 (hi + lo, 2 mt each)
            uint32_t ah[2][4], al[2][4];
            LDSM4(ah[0], rb + a_off[0]);
            LDSM4(ah[1], rb + a_off[1]);
            LDSM4(al[0], rb + a_off[0] + 2048);   // ALO = AHIW + 512 words
            LDSM4(al[1], rb + a_off[1] + 2048);

            // ---- B fragments + MMAs in two nt-halves
#pragma unroll
            for (int sub = 0; sub < 2; ++sub) {
                uint32_t bh[4][2], bl[4][2];
                LDSM4(&bh[0][0], rb + b_off[sub][0]);
                LDSM4(&bh[2][0], rb + b_off[sub][1]);
                LDSM4(&bl[0][0], rb + b_off[sub][0] + 4096);  // BLO = BHIW + 1024
                LDSM4(&bl[2][0], rb + b_off[sub][1] + 4096);
#pragma unroll
                for (int mt = 0; mt < 2; ++mt)
#pragma unroll
                    for (int nt4 = 0; nt4 < 4; ++nt4) {
                        float* acc = c[mt][sub * 4 + nt4];
                        MMA(acc, ah[mt], bh[nt4]);   // hi*hi
                        MMA(acc, al[mt], bh[nt4]);   // lo*hi
                        MMA(acc, ah[mt], bl[nt4]);   // hi*lo
                    }
            }
            if (++buf_c == NBUF) buf_c = 0;
        }

        // ---- running argmin over this k-tile (k strictly ascending per thread)
#pragma unroll
        for (int nt = 0; nt < 8; ++nt)
#pragma unroll
            for (int q = 0; q < 2; ++q) {
                const int k = kt * KT + wk * 64 + nt * 8 + 2 * l4 + q;
                const float e2v = __ldg(&g_e2[k]);
#pragma unroll
                for (int mt = 0; mt < 2; ++mt) {
                    float v0 = fmaf(-2.f, c[mt][nt][q], e2v);       // row lr
                    if (v0 < bestv[mt * 2])     { bestv[mt * 2] = v0;     bestk[mt * 2] = k; }
                    float v1 = fmaf(-2.f, c[mt][nt][2 + q], e2v);   // row lr+8
                    if (v1 < bestv[mt * 2 + 1]) { bestv[mt * 2 + 1] = v1; bestk[mt * 2 + 1] = k; }
                }
            }
    }

    // ---- reduce across the 4 lanes of each quad (same o rows, different k)
#pragma unroll
    for (int i = 0; i < 4; ++i) {
        float v = bestv[i];
        int   k = bestk[i];
#pragma unroll
        for (int off = 1; off <= 2; off <<= 1) {
            float ov = __shfl_xor_sync(0xFFFFFFFFu, v, off);
            int   ok = __shfl_xor_sync(0xFFFFFFFFu, k, off);
            if (ov < v || (ov == v && ok < k)) { v = ov; k = ok; }
        }
        if (l4 == 0) {
            const int o = wo * 32 + (i >> 1) * 16 + (i & 1) * 8 + lr;
            smf[REDVW + wk * OT + o] = v;
            reinterpret_cast<int*>(smw)[REDKW + wk * OT + o] = k;
        }
    }
    __syncthreads();

    // ---- combine 2 k-warps (wk ascending = k ascending: strict < keeps first)
    int* ksarr = reinterpret_cast<int*>(smw) + KSOW;
    if (tid < OT) {
        float v = smf[REDVW + tid];
        int   k = reinterpret_cast<int*>(smw)[REDKW + tid];
        float ov = smf[REDVW + OT + tid];
        int   ok = reinterpret_cast<int*>(smw)[REDKW + OT + tid];
        if (ov < v) { v = ov; k = ok; }
        ksarr[tid] = k;
        if (argout) argout[b * OO + o0 + tid] = (float)k;
    }
    __syncthreads();

    // ---- gather quant[b,d,o] = emb[d, ks[o]]
    if (quant) {
        float* qb = quant + (size_t)b * DD * OO + o0;
        for (int idx = tid; idx < DD * OT; idx += NT) {
            int d = idx >> 6;
            int o = idx & (OT - 1);
            qb[d * OO + o] = emb[d * KK + ksarr[o]];
        }
    }
}

// ---------------------------------------------------------------------------
extern "C" void kernel_launch(void* const* d_in, const int* in_sizes, int n_in,
                              void* d_out, int out_size) {
    const float* x   = (const float*)d_in[0];
    const float* emb = (const float*)d_in[1];
    float* out = (float*)d_out;

    const int QN = BB * DD * OO;
    const int AN = BB * OO;

    float* quant  = nullptr;
    float* argout = nullptr;
    if (out_size >= QN) {
        quant = out;
        if (out_size >= QN + AN) argout = out + QN;
    } else if (out_size >= AN) {
        argout = out;
    }

    cudaFuncSetAttribute(vq_tc, cudaFuncAttributeMaxDynamicSharedMemorySize, SM_BYTES);

    e2_kernel<<<KK / 32, 256>>>(emb);
    splitT_emb<<<dim3(KK / 32, DD / 32), 256>>>(emb);
    splitT_x<<<dim3(OO / 32, DD / 32, BB), 256>>>(x);

    dim3 grid(OO / OT, BB);
    vq_tc<<<grid, NT, SM_BYTES>>>(emb, quant, argout);
}